// round 9
// baseline (speedup 1.0000x reference)
#include <cuda_runtime.h>
#include <math.h>

#define BB 2
#define SS 2048
#define EE 1024
#define HH 16
#define HD 64
#define MTOT (BB*SS)
#define SCALE 0.125f   // 1/sqrt(64)

// Scratch (allocation-free rule): device globals
__device__ float g_q[MTOT * EE];     // tf32-rounded Q projection
__device__ float g_k[MTOT * EE];
__device__ float g_v[MTOT * EE];
__device__ float g_att[MTOT * EE];   // tf32-rounded attention output
__device__ float g_xq[MTOT * EE];    // tf32-rounded inputs
__device__ float g_xk[MTOT * EE];
__device__ float g_xv[MTOT * EE];
__device__ float g_wq[EE * EE];      // tf32-rounded weights
__device__ float g_wk[EE * EE];
__device__ float g_wv[EE * EE];
__device__ float g_wo[EE * EE];

// ---------------------------------------------------------------------------
// helpers
// ---------------------------------------------------------------------------
__device__ __forceinline__ unsigned f2tf(float f) {
    unsigned r;
    asm("cvt.rna.tf32.f32 %0, %1;" : "=r"(r) : "f"(f));
    return r;
}

__device__ __forceinline__ void mma_tf32(float c[4], const unsigned a[4], const unsigned b[2]) {
    asm volatile(
        "mma.sync.aligned.m16n8k8.row.col.f32.tf32.tf32.f32 "
        "{%0,%1,%2,%3}, {%4,%5,%6,%7}, {%8,%9}, {%0,%1,%2,%3};"
        : "+f"(c[0]), "+f"(c[1]), "+f"(c[2]), "+f"(c[3])
        : "r"(a[0]), "r"(a[1]), "r"(a[2]), "r"(a[3]), "r"(b[0]), "r"(b[1]));
}

__device__ __forceinline__ void cpa16(unsigned dst, const void* src) {
    asm volatile("cp.async.cg.shared.global [%0], [%1], 16;" :: "r"(dst), "l"(src) : "memory");
}
__device__ __forceinline__ void cp_commit() { asm volatile("cp.async.commit_group;" ::: "memory"); }
__device__ __forceinline__ void cp_wait0() { asm volatile("cp.async.wait_group 0;" ::: "memory"); }
__device__ __forceinline__ void cp_wait1() { asm volatile("cp.async.wait_group 1;" ::: "memory"); }
__device__ __forceinline__ void cp_wait2() { asm volatile("cp.async.wait_group 2;" ::: "memory"); }

// ---------------------------------------------------------------------------
// Prepass: round 7 tensors to tf32 copies
// ---------------------------------------------------------------------------
struct RoundArgs {
    const float* src[7];
    float*       dst[7];
    int          n4[7];
};

__global__ __launch_bounds__(256) void tf32_round(RoundArgs a) {
    const int z = blockIdx.y;
    const int n4 = a.n4[z];
    const float4* s = (const float4*)a.src[z];
    float4* d = (float4*)a.dst[z];
    for (int i = blockIdx.x * blockDim.x + threadIdx.x; i < n4;
         i += gridDim.x * blockDim.x) {
        float4 v = s[i];
        v.x = __uint_as_float(f2tf(v.x));
        v.y = __uint_as_float(f2tf(v.y));
        v.z = __uint_as_float(f2tf(v.z));
        v.w = __uint_as_float(f2tf(v.w));
        d[i] = v;
    }
}

// ---------------------------------------------------------------------------
// GEMM: C[M,N] = A[M,K] @ W[N,K]^T + bias   (A, W pre-rounded tf32)
// R2's exact compute loop: CTA 128x128x32, 256 threads (8 warps 2Mx4N),
// warp tile 64x32, GSTR=36 (conflict-free fragment reads).
// Staging via cp.async, 3 stages, one __syncthreads per K-iter.  (R6 WIN)
// ---------------------------------------------------------------------------
#define GSTR 36
#define STGW 9216            // words per stage: A 128*36, B 128*36
#define STGB (STGW * 4)      // bytes per stage

struct QKVArgs {
    const float* A[3];
    const float* W[3];
    const float* bias[3];
    float*       C[3];
};

template<bool RND>
__device__ __forceinline__ void gemm_body(
    const float* __restrict__ A, const float* __restrict__ W,
    const float* __restrict__ bias, float* __restrict__ C)
{
    extern __shared__ unsigned sm[];   // 3 stages x 9216 words = 108 KB
    const unsigned smem_u = (unsigned)__cvta_generic_to_shared(sm);

    const int tid  = threadIdx.x;
    const int warp = tid >> 5, lane = tid & 31;
    const int g = lane >> 2, t = lane & 3;
    const int wm = warp & 1, wn = warp >> 1;     // 2 x 4 warps, warp tile 64x32
    const int bm = blockIdx.y * 128, bn = blockIdx.x * 128;

    // staging constants: thread covers rows m0+32i (i=0..3), k-quad kq (16B)
    const int kq = tid & 7;          // fixed k-quad
    const int m0 = tid >> 3;         // 0..31
    const float* Asrc = A + (size_t)(bm + m0) * EE + kq * 4;
    const float* Wsrc = W + (size_t)(bn + m0) * EE + kq * 4;
    const unsigned dA = smem_u + (m0 * GSTR + kq * 4) * 4;  // + i*4608B + stage*STGB
    const unsigned dB = dA + 4608 * 4;                      // B block at word 4608

    float acc[4][4][4] = {};
    const int NK = EE / 32;          // 32

    // prologue: stage tiles 0 and 1
    #pragma unroll
    for (int p = 0; p < 2; p++) {
        const unsigned so = p * STGB;
        const int ko = p * 32;
        #pragma unroll
        for (int i = 0; i < 4; i++) {
            cpa16(dA + so + i * 4608, Asrc + ko + (size_t)i * 32 * EE);
            cpa16(dB + so + i * 4608, Wsrc + ko + (size_t)i * 32 * EE);
        }
        cp_commit();
    }

    int st = 0;   // stage holding tile kt
    for (int kt = 0; kt < NK; kt++) {
        if (kt + 1 < NK) cp_wait1(); else cp_wait0();
        __syncthreads();

        // prefetch tile kt+2 into stage (st+2)%3 (its readers done at kt-1)
        if (kt + 2 < NK) {
            const int s2 = (st + 2 >= 3) ? st - 1 : st + 2;
            const unsigned so = s2 * STGB;
            const int ko = (kt + 2) * 32;
            #pragma unroll
            for (int i = 0; i < 4; i++) {
                cpa16(dA + so + i * 4608, Asrc + ko + (size_t)i * 32 * EE);
                cpa16(dB + so + i * 4608, Wsrc + ko + (size_t)i * 32 * EE);
            }
            cp_commit();
        }

        // ---- R2 compute loop: 4 k-steps of 8
        const unsigned* Asm = sm + st * STGW;
        const unsigned* Bsm = Asm + 4608;
        #pragma unroll
        for (int ksc = 0; ksc < 4; ksc++) {
            unsigned af[4][4], bf[4][2];
            #pragma unroll
            for (int mi = 0; mi < 4; mi++) {
                const int row = wm * 64 + mi * 16;
                af[mi][0] = Asm[(row + g)     * GSTR + ksc * 8 + t];
                af[mi][1] = Asm[(row + g + 8) * GSTR + ksc * 8 + t];
                af[mi][2] = Asm[(row + g)     * GSTR + ksc * 8 + t + 4];
                af[mi][3] = Asm[(row + g + 8) * GSTR + ksc * 8 + t + 4];
            }
            #pragma unroll
            for (int ni = 0; ni < 4; ni++) {
                const int col = wn * 32 + ni * 8 + g;
                bf[ni][0] = Bsm[col * GSTR + ksc * 8 + t];
                bf[ni][1] = Bsm[col * GSTR + ksc * 8 + t + 4];
            }
            #pragma unroll
            for (int mi = 0; mi < 4; mi++)
                #pragma unroll
                for (int ni = 0; ni < 4; ni++)
                    mma_tf32(acc[mi][ni], af[mi], bf[ni]);
        }
        st = (st + 1 >= 3) ? 0 : st + 1;
    }

    // ---- epilogue: add bias (fp32), optional tf32 round, store
    #pragma unroll
    for (int mi = 0; mi < 4; mi++) {
        #pragma unroll
        for (int r2 = 0; r2 < 2; r2++) {
            const int m = bm + wm * 64 + mi * 16 + g + r2 * 8;
            #pragma unroll
            for (int ni = 0; ni < 4; ni++) {
                const int n = bn + wn * 32 + ni * 8 + 2 * t;
                float2 bv = *(const float2*)(bias + n);
                float2 o;
                o.x = acc[mi][ni][r2 * 2 + 0] + bv.x;
                o.y = acc[mi][ni][r2 * 2 + 1] + bv.y;
                if (RND) {
                    o.x = __uint_as_float(f2tf(o.x));
                    o.y = __uint_as_float(f2tf(o.y));
                }
                *(float2*)(C + (size_t)m * EE + n) = o;
            }
        }
    }
}

__global__ __launch_bounds__(256, 2) void qkv_gemm(QKVArgs args) {
    const int z = blockIdx.z;
    gemm_body<true>(args.A[z], args.W[z], args.bias[z], args.C[z]);
}

__global__ __launch_bounds__(256, 2) void out_gemm(const float* __restrict__ A,
                                                   const float* __restrict__ W,
                                                   const float* __restrict__ bias,
                                                   float* __restrict__ C) {
    gemm_body<false>(A, W, bias, C);
}

// ---------------------------------------------------------------------------
// Flash attention, tf32 mma, cp.async pipelined staging (R7).
// R9: 256 threads / 8 warps / 128 q-rows per CTA (warp algorithm unchanged:
// each warp owns 16 rows). K/V staging + syncs amortized over 2x q-rows.
// smem: Ks 64x68 + Vs 64x68 + Ps 128x68 = 17408 words = 68 KB, 2 CTAs/SM.
// ---------------------------------------------------------------------------
#define ASTR 68

__global__ __launch_bounds__(256, 2) void attn_tc() {
    extern __shared__ unsigned smem[];
    unsigned* Ks = smem;                 // 64*68 = 4352 words
    unsigned* Vs = smem + 4352;          // 4352 words
    unsigned* Ps = smem + 8704;          // 128*68 = 8704 words (Q stage, then P)
    const unsigned smem_u = (unsigned)__cvta_generic_to_shared(smem);
    const unsigned Ks_u = smem_u;
    const unsigned Vs_u = smem_u + 4352 * 4;
    const unsigned Ps_u = smem_u + 8704 * 4;

    const int tid  = threadIdx.x;
    const int warp = tid >> 5, lane = tid & 31;
    const int g = lane >> 2, t = lane & 3;
    const int bh = blockIdx.x;
    const int b = bh >> 4, h = bh & 15;
    const int q0 = blockIdx.y * 128;

    const size_t base = (size_t)b * SS * EE + (size_t)h * HD;

    // staging thread constants: 256 threads, rows r0 + 16i, 16B chunk c4
    const int r0 = tid >> 4;         // 0..15
    const int c4 = tid & 15;         // 0..15
    const unsigned dstW = (unsigned)((r0 * ASTR + c4 * 4) * 4);  // byte offset

    const float* qsrc = g_q + base + (size_t)(q0 + r0) * EE + c4 * 4;
    const float* ksrc = g_k + base + (size_t)r0 * EE + c4 * 4;
    const float* vsrc = g_v + base + (size_t)r0 * EE + c4 * 4;

    // ---- prologue: Q(128 rows) -> Ps, K0 -> Ks, V0 -> Vs
    #pragma unroll
    for (int i = 0; i < 8; i++)       // Q: rows r0 + 16i, i=0..7
        cpa16(Ps_u + dstW + i * 16 * ASTR * 4, qsrc + (size_t)i * 16 * EE);
    cp_commit();
    #pragma unroll
    for (int i = 0; i < 4; i++)       // K: rows r0 + 16i, i=0..3
        cpa16(Ks_u + dstW + i * 16 * ASTR * 4, ksrc + (size_t)i * 16 * EE);
    cp_commit();
    #pragma unroll
    for (int i = 0; i < 4; i++)
        cpa16(Vs_u + dstW + i * 16 * ASTR * 4, vsrc + (size_t)i * 16 * EE);
    cp_commit();

    cp_wait2();          // Q arrived; K0, V0 still pending
    __syncthreads();

    // pull Q A-fragments (warp-local rows), fold SCALE (power of 2: exact)
    unsigned qf[8][4];
    {
        const int m = warp * 16;
        #pragma unroll
        for (int ks = 0; ks < 8; ks++) {
            qf[ks][0] = Ps[(m + g)     * ASTR + ks * 8 + t];
            qf[ks][1] = Ps[(m + g + 8) * ASTR + ks * 8 + t];
            qf[ks][2] = Ps[(m + g)     * ASTR + ks * 8 + t + 4];
            qf[ks][3] = Ps[(m + g + 8) * ASTR + ks * 8 + t + 4];
            #pragma unroll
            for (int j = 0; j < 4; j++)
                qf[ks][j] = __float_as_uint(__uint_as_float(qf[ks][j]) * SCALE);
        }
    }

    float o[8][4] = {};
    float mrow0 = -1e30f, mrow1 = -1e30f, lrow0 = 0.f, lrow1 = 0.f;

    const int NT = SS / 64;
    for (int kt = 0; kt < NT; kt++) {
        // ---- K[kt] ready (V[kt] may still be in flight)
        cp_wait1();
        __syncthreads();

        // ---- S = Q @ K^T  (per warp: 16 x 64)
        float s[8][4] = {};
        #pragma unroll
        for (int ks = 0; ks < 8; ks++) {
            #pragma unroll
            for (int ni = 0; ni < 8; ni++) {
                unsigned bf[2];
                const int n = ni * 8 + g;                 // kv index
                bf[0] = Ks[n * ASTR + ks * 8 + t];
                bf[1] = Ks[n * ASTR + ks * 8 + t + 4];
                mma_tf32(s[ni], qf[ks], bf);
            }
        }

        // ---- online softmax (rows g and g+8; reduce over the 4 lanes of t)
        float mx0 = -1e30f, mx1 = -1e30f;
        #pragma unroll
        for (int ni = 0; ni < 8; ni++) {
            mx0 = fmaxf(mx0, fmaxf(s[ni][0], s[ni][1]));
            mx1 = fmaxf(mx1, fmaxf(s[ni][2], s[ni][3]));
        }
        mx0 = fmaxf(mx0, __shfl_xor_sync(0xffffffffu, mx0, 1));
        mx0 = fmaxf(mx0, __shfl_xor_sync(0xffffffffu, mx0, 2));
        mx1 = fmaxf(mx1, __shfl_xor_sync(0xffffffffu, mx1, 1));
        mx1 = fmaxf(mx1, __shfl_xor_sync(0xffffffffu, mx1, 2));

        float mn0 = fmaxf(mrow0, mx0), mn1 = fmaxf(mrow1, mx1);
        float c0 = __expf(mrow0 - mn0), c1 = __expf(mrow1 - mn1);
        float sum0 = 0.f, sum1 = 0.f;
        #pragma unroll
        for (int ni = 0; ni < 8; ni++) {
            s[ni][0] = __expf(s[ni][0] - mn0);
            s[ni][1] = __expf(s[ni][1] - mn0);
            s[ni][2] = __expf(s[ni][2] - mn1);
            s[ni][3] = __expf(s[ni][3] - mn1);
            sum0 += s[ni][0] + s[ni][1];
            sum1 += s[ni][2] + s[ni][3];
        }
        sum0 += __shfl_xor_sync(0xffffffffu, sum0, 1);
        sum0 += __shfl_xor_sync(0xffffffffu, sum0, 2);
        sum1 += __shfl_xor_sync(0xffffffffu, sum1, 1);
        sum1 += __shfl_xor_sync(0xffffffffu, sum1, 2);
        lrow0 = lrow0 * c0 + sum0;  mrow0 = mn0;
        lrow1 = lrow1 * c1 + sum1;  mrow1 = mn1;
        #pragma unroll
        for (int ni = 0; ni < 8; ni++) {
            o[ni][0] *= c0; o[ni][1] *= c0;
            o[ni][2] *= c1; o[ni][3] *= c1;
        }

        // ---- all warps done reading Ks; prefetch K[kt+1] (overlaps PV)
        __syncthreads();
        if (kt + 1 < NT) {
            const float* kn = ksrc + (size_t)(kt + 1) * 64 * EE;
            #pragma unroll
            for (int i = 0; i < 4; i++)
                cpa16(Ks_u + dstW + i * 16 * ASTR * 4, kn + (size_t)i * 16 * EE);
            cp_commit();
            cp_wait1();   // V[kt] arrived (K[kt+1] still pending)
        } else {
            cp_wait0();   // V[kt] arrived
        }
        __syncthreads();

        // ---- write P (tf32) to warp-local rows of Ps
        {
            const int m = warp * 16;
            #pragma unroll
            for (int ni = 0; ni < 8; ni++) {
                uint2 w0 = make_uint2(f2tf(s[ni][0]), f2tf(s[ni][1]));
                uint2 w1 = make_uint2(f2tf(s[ni][2]), f2tf(s[ni][3]));
                *(uint2*)&Ps[(m + g)     * ASTR + ni * 8 + 2 * t] = w0;
                *(uint2*)&Ps[(m + g + 8) * ASTR + ni * 8 + 2 * t] = w1;
            }
        }
        __syncwarp();

        // ---- O += P @ V  (A from Ps, B = Vs[j][d])
        {
            const int m = warp * 16;
            #pragma unroll
            for (int ks = 0; ks < 8; ks++) {
                unsigned af[4];
                af[0] = Ps[(m + g)     * ASTR + ks * 8 + t];
                af[1] = Ps[(m + g + 8) * ASTR + ks * 8 + t];
                af[2] = Ps[(m + g)     * ASTR + ks * 8 + t + 4];
                af[3] = Ps[(m + g + 8) * ASTR + ks * 8 + t + 4];
                #pragma unroll
                for (int ni = 0; ni < 8; ni++) {
                    unsigned bf[2];
                    const int n = ni * 8 + g;             // d index
                    bf[0] = Vs[(ks * 8 + t)     * ASTR + n];
                    bf[1] = Vs[(ks * 8 + t + 4) * ASTR + n];
                    mma_tf32(o[ni], af, bf);
                }
            }
        }
        __syncthreads();   // all warps done reading Vs

        // ---- prefetch V[kt+1] (overlaps next S phase)
        if (kt + 1 < NT) {
            const float* vn = vsrc + (size_t)(kt + 1) * 64 * EE;
            #pragma unroll
            for (int i = 0; i < 4; i++)
                cpa16(Vs_u + dstW + i * 16 * ASTR * 4, vn + (size_t)i * 16 * EE);
            cp_commit();
        }
    }

    // ---- normalize, round to tf32 (consumed by cp.async out_gemm), store
    float inv0 = 1.f / lrow0, inv1 = 1.f / lrow1;
    const int r0q = q0 + warp * 16 + g;
    #pragma unroll
    for (int ni = 0; ni < 8; ni++) {
        const int d = h * HD + ni * 8 + 2 * t;
        float2 w0, w1;
        w0.x = __uint_as_float(f2tf(o[ni][0] * inv0));
        w0.y = __uint_as_float(f2tf(o[ni][1] * inv0));
        w1.x = __uint_as_float(f2tf(o[ni][2] * inv1));
        w1.y = __uint_as_float(f2tf(o[ni][3] * inv1));
        *(float2*)(g_att + (size_t)(b * SS + r0q)     * EE + d) = w0;
        *(float2*)(g_att + (size_t)(b * SS + r0q + 8) * EE + d) = w1;
    }
}

// ---------------------------------------------------------------------------
// Launch
// ---------------------------------------------------------------------------
extern "C" void kernel_launch(void* const* d_in, const int* in_sizes, int n_in,
                              void* d_out, int out_size)
{
    const float* query = (const float*)d_in[0];
    const float* key_  = (const float*)d_in[1];
    const float* value = (const float*)d_in[2];
    const float* Wq = (const float*)d_in[3];
    const float* bq = (const float*)d_in[4];
    const float* Wk = (const float*)d_in[5];
    const float* bk = (const float*)d_in[6];
    const float* Wv = (const float*)d_in[7];
    const float* bv = (const float*)d_in[8];
    const float* Wo = (const float*)d_in[9];
    const float* bo = (const float*)d_in[10];
    float* out = (float*)d_out;

    float *q, *k, *v, *att, *xq, *xk, *xv, *wq, *wk, *wv, *wo;
    cudaGetSymbolAddress((void**)&q,   g_q);
    cudaGetSymbolAddress((void**)&k,   g_k);
    cudaGetSymbolAddress((void**)&v,   g_v);
    cudaGetSymbolAddress((void**)&att, g_att);
    cudaGetSymbolAddress((void**)&xq,  g_xq);
    cudaGetSymbolAddress((void**)&xk,  g_xk);
    cudaGetSymbolAddress((void**)&xv,  g_xv);
    cudaGetSymbolAddress((void**)&wq,  g_wq);
    cudaGetSymbolAddress((void**)&wk,  g_wk);
    cudaGetSymbolAddress((void**)&wv,  g_wv);
    cudaGetSymbolAddress((void**)&wo,  g_wo);

    static bool attr_done = false;
    if (!attr_done) {
        cudaFuncSetAttribute(qkv_gemm, cudaFuncAttributeMaxDynamicSharedMemorySize, 3 * STGB);
        cudaFuncSetAttribute(out_gemm, cudaFuncAttributeMaxDynamicSharedMemorySize, 3 * STGB);
        cudaFuncSetAttribute(attn_tc,  cudaFuncAttributeMaxDynamicSharedMemorySize, 17408 * 4);
        attr_done = true;
    }

    // 1) prepass: round inputs + weights to tf32
    RoundArgs ra;
    ra.src[0] = query; ra.dst[0] = xq; ra.n4[0] = MTOT * EE / 4;
    ra.src[1] = key_;  ra.dst[1] = xk; ra.n4[1] = MTOT * EE / 4;
    ra.src[2] = value; ra.dst[2] = xv; ra.n4[2] = MTOT * EE / 4;
    ra.src[3] = Wq;    ra.dst[3] = wq; ra.n4[3] = EE * EE / 4;
    ra.src[4] = Wk;    ra.dst[4] = wk; ra.n4[4] = EE * EE / 4;
    ra.src[5] = Wv;    ra.dst[5] = wv; ra.n4[5] = EE * EE / 4;
    ra.src[6] = Wo;    ra.dst[6] = wo; ra.n4[6] = EE * EE / 4;
    tf32_round<<<dim3(1024, 7), 256>>>(ra);

    // 2) QKV projections
    QKVArgs args;
    args.A[0] = xq; args.A[1] = xk; args.A[2] = xv;
    args.W[0] = wq; args.W[1] = wk; args.W[2] = wv;
    args.bias[0] = bq; args.bias[1] = bk; args.bias[2] = bv;
    args.C[0] = q; args.C[1] = k; args.C[2] = v;
    qkv_gemm<<<dim3(EE / 128, MTOT / 128, 3), 256, 3 * STGB>>>(args);

    // 3) attention: 128 q-rows per CTA, 256 threads
    attn_tc<<<dim3(BB * HH, SS / 128), 256, 17408 * 4>>>();

    // 4) output projection
    out_gemm<<<dim3(EE / 128, MTOT / 128), 256, 3 * STGB>>>(att, wo, bo, out);
}

// round 10
// speedup vs baseline: 1.0900x; 1.0900x over previous
#include <cuda_runtime.h>
#include <math.h>

#define BB 2
#define SS 2048
#define EE 1024
#define HH 16
#define HD 64
#define MTOT (BB*SS)
#define SCALE 0.125f   // 1/sqrt(64)

// Scratch (allocation-free rule): device globals
__device__ float g_q[MTOT * EE];     // tf32-rounded Q projection
__device__ float g_k[MTOT * EE];     // tf32-rounded K projection, PAIR-PERMUTED cols
__device__ float g_v[MTOT * EE];
__device__ float g_att[MTOT * EE];   // tf32-rounded attention output
__device__ float g_xq[MTOT * EE];    // tf32-rounded inputs
__device__ float g_xk[MTOT * EE];
__device__ float g_xv[MTOT * EE];
__device__ float g_wq[EE * EE];      // tf32-rounded weights
__device__ float g_wk[EE * EE];
__device__ float g_wv[EE * EE];
__device__ float g_wo[EE * EE];

// ---------------------------------------------------------------------------
// helpers
// ---------------------------------------------------------------------------
__device__ __forceinline__ unsigned f2tf(float f) {
    unsigned r;
    asm("cvt.rna.tf32.f32 %0, %1;" : "=r"(r) : "f"(f));
    return r;
}

__device__ __forceinline__ void mma_tf32(float c[4], const unsigned a[4], const unsigned b[2]) {
    asm volatile(
        "mma.sync.aligned.m16n8k8.row.col.f32.tf32.tf32.f32 "
        "{%0,%1,%2,%3}, {%4,%5,%6,%7}, {%8,%9}, {%0,%1,%2,%3};"
        : "+f"(c[0]), "+f"(c[1]), "+f"(c[2]), "+f"(c[3])
        : "r"(a[0]), "r"(a[1]), "r"(a[2]), "r"(a[3]), "r"(b[0]), "r"(b[1]));
}

__device__ __forceinline__ void cpa16(unsigned dst, const void* src) {
    asm volatile("cp.async.cg.shared.global [%0], [%1], 16;" :: "r"(dst), "l"(src) : "memory");
}
__device__ __forceinline__ void cp_commit() { asm volatile("cp.async.commit_group;" ::: "memory"); }
__device__ __forceinline__ void cp_wait0() { asm volatile("cp.async.wait_group 0;" ::: "memory"); }
__device__ __forceinline__ void cp_wait1() { asm volatile("cp.async.wait_group 1;" ::: "memory"); }
__device__ __forceinline__ void cp_wait2() { asm volatile("cp.async.wait_group 2;" ::: "memory"); }

// ---------------------------------------------------------------------------
// Prepass: round 7 tensors to tf32 copies
// ---------------------------------------------------------------------------
struct RoundArgs {
    const float* src[7];
    float*       dst[7];
    int          n4[7];
};

__global__ __launch_bounds__(256) void tf32_round(RoundArgs a) {
    const int z = blockIdx.y;
    const int n4 = a.n4[z];
    const float4* s = (const float4*)a.src[z];
    float4* d = (float4*)a.dst[z];
    for (int i = blockIdx.x * blockDim.x + threadIdx.x; i < n4;
         i += gridDim.x * blockDim.x) {
        float4 v = s[i];
        v.x = __uint_as_float(f2tf(v.x));
        v.y = __uint_as_float(f2tf(v.y));
        v.z = __uint_as_float(f2tf(v.z));
        v.w = __uint_as_float(f2tf(v.w));
        d[i] = v;
    }
}

// ---------------------------------------------------------------------------
// GEMM: C[M,N] = A[M,K] @ W[N,K]^T + bias   (A, W pre-rounded tf32)
// R2's exact compute loop: CTA 128x128x32, 256 threads (8 warps 2Mx4N),
// warp tile 64x32, GSTR=36 (conflict-free fragment reads).
// Staging via cp.async, 3 stages, one __syncthreads per K-iter.  (R6 WIN)
// KPERM: K output stored pair-permuted within each 8-col group so attention
// can read B-fragments with LDS.64  (pos(j) = (j%4)*2 + j/4).
// ---------------------------------------------------------------------------
#define GSTR 36
#define STGW 9216            // words per stage: A 128*36, B 128*36
#define STGB (STGW * 4)      // bytes per stage

struct QKVArgs {
    const float* A[3];
    const float* W[3];
    const float* bias[3];
    float*       C[3];
};

template<bool RND, bool KPERM>
__device__ __forceinline__ void gemm_body(
    const float* __restrict__ A, const float* __restrict__ W,
    const float* __restrict__ bias, float* __restrict__ C)
{
    extern __shared__ unsigned sm[];   // 3 stages x 9216 words = 108 KB
    const unsigned smem_u = (unsigned)__cvta_generic_to_shared(sm);

    const int tid  = threadIdx.x;
    const int warp = tid >> 5, lane = tid & 31;
    const int g = lane >> 2, t = lane & 3;
    const int wm = warp & 1, wn = warp >> 1;     // 2 x 4 warps, warp tile 64x32
    const int bm = blockIdx.y * 128, bn = blockIdx.x * 128;

    // staging constants: thread covers rows m0+32i (i=0..3), k-quad kq (16B)
    const int kq = tid & 7;          // fixed k-quad
    const int m0 = tid >> 3;         // 0..31
    const float* Asrc = A + (size_t)(bm + m0) * EE + kq * 4;
    const float* Wsrc = W + (size_t)(bn + m0) * EE + kq * 4;
    const unsigned dA = smem_u + (m0 * GSTR + kq * 4) * 4;  // + i*4608B + stage*STGB
    const unsigned dB = dA + 4608 * 4;                      // B block at word 4608

    float acc[4][4][4] = {};
    const int NK = EE / 32;          // 32

    // prologue: stage tiles 0 and 1
    #pragma unroll
    for (int p = 0; p < 2; p++) {
        const unsigned so = p * STGB;
        const int ko = p * 32;
        #pragma unroll
        for (int i = 0; i < 4; i++) {
            cpa16(dA + so + i * 4608, Asrc + ko + (size_t)i * 32 * EE);
            cpa16(dB + so + i * 4608, Wsrc + ko + (size_t)i * 32 * EE);
        }
        cp_commit();
    }

    int st = 0;   // stage holding tile kt
    for (int kt = 0; kt < NK; kt++) {
        if (kt + 1 < NK) cp_wait1(); else cp_wait0();
        __syncthreads();

        // prefetch tile kt+2 into stage (st+2)%3 (its readers done at kt-1)
        if (kt + 2 < NK) {
            const int s2 = (st + 2 >= 3) ? st - 1 : st + 2;
            const unsigned so = s2 * STGB;
            const int ko = (kt + 2) * 32;
            #pragma unroll
            for (int i = 0; i < 4; i++) {
                cpa16(dA + so + i * 4608, Asrc + ko + (size_t)i * 32 * EE);
                cpa16(dB + so + i * 4608, Wsrc + ko + (size_t)i * 32 * EE);
            }
            cp_commit();
        }

        // ---- R2 compute loop: 4 k-steps of 8
        const unsigned* Asm = sm + st * STGW;
        const unsigned* Bsm = Asm + 4608;
        #pragma unroll
        for (int ksc = 0; ksc < 4; ksc++) {
            unsigned af[4][4], bf[4][2];
            #pragma unroll
            for (int mi = 0; mi < 4; mi++) {
                const int row = wm * 64 + mi * 16;
                af[mi][0] = Asm[(row + g)     * GSTR + ksc * 8 + t];
                af[mi][1] = Asm[(row + g + 8) * GSTR + ksc * 8 + t];
                af[mi][2] = Asm[(row + g)     * GSTR + ksc * 8 + t + 4];
                af[mi][3] = Asm[(row + g + 8) * GSTR + ksc * 8 + t + 4];
            }
            #pragma unroll
            for (int ni = 0; ni < 4; ni++) {
                const int col = wn * 32 + ni * 8 + g;
                bf[ni][0] = Bsm[col * GSTR + ksc * 8 + t];
                bf[ni][1] = Bsm[col * GSTR + ksc * 8 + t + 4];
            }
            #pragma unroll
            for (int mi = 0; mi < 4; mi++)
                #pragma unroll
                for (int ni = 0; ni < 4; ni++)
                    mma_tf32(acc[mi][ni], af[mi], bf[ni]);
        }
        st = (st + 1 >= 3) ? 0 : st + 1;
    }

    // ---- epilogue: add bias (fp32), optional tf32 round, store
    #pragma unroll
    for (int mi = 0; mi < 4; mi++) {
        #pragma unroll
        for (int r2 = 0; r2 < 2; r2++) {
            const int m = bm + wm * 64 + mi * 16 + g + r2 * 8;
            #pragma unroll
            for (int ni = 0; ni < 4; ni++) {
                const int n = bn + wn * 32 + ni * 8 + 2 * t;
                float2 bv = *(const float2*)(bias + n);
                float2 o;
                o.x = acc[mi][ni][r2 * 2 + 0] + bv.x;
                o.y = acc[mi][ni][r2 * 2 + 1] + bv.y;
                if (RND) {
                    o.x = __uint_as_float(f2tf(o.x));
                    o.y = __uint_as_float(f2tf(o.y));
                }
                if (KPERM) {
                    // pair-permute within 8-col group: pos(j) = (j%4)*2 + j/4
                    const int jj = n & 7;                         // = 2t
                    const int p0 = ((jj & 3) << 1) + (jj >> 2);   // pos of col n
                    float* dst = C + (size_t)m * EE + (n & ~7);
                    dst[p0]     = o.x;                            // col n
                    dst[p0 + 2] = o.y;                            // col n+1
                } else {
                    *(float2*)(C + (size_t)m * EE + n) = o;
                }
            }
        }
    }
}

__global__ __launch_bounds__(256, 2) void qkv_gemm(QKVArgs args) {
    const int z = blockIdx.z;
    if (z == 1)
        gemm_body<true, true>(args.A[z], args.W[z], args.bias[z], args.C[z]);
    else
        gemm_body<true, false>(args.A[z], args.W[z], args.bias[z], args.C[z]);
}

__global__ __launch_bounds__(256, 2) void out_gemm(const float* __restrict__ A,
                                                   const float* __restrict__ W,
                                                   const float* __restrict__ bias,
                                                   float* __restrict__ C) {
    gemm_body<false, false>(A, W, bias, C);
}

// ---------------------------------------------------------------------------
// Flash attention, tf32 mma, cp.async pipelined staging (R7/R8 base).
// Block = (b, h, 64 q-rows), 128 threads (4 warps, 16 rows each), 4 CTAs/SM.
// R10: g_k is pair-permuted -> Ks stride 72, S-phase B-fragments via LDS.64
// (banks 8g+2t+8ks: 16 distinct/half-warp -> conflict-free).
// ---------------------------------------------------------------------------
#define ASTR 68
#define KSTR 72
// smem words: Ks 64*72=4608 | Vs 64*68=4352 | Ps 64*68=4352  -> 13312 (52 KB)
#define ATT_SMEM_W 13312

__global__ __launch_bounds__(128, 4) void attn_tc() {
    extern __shared__ unsigned smem[];
    unsigned* Ks = smem;                 // 4608 words (stride 72)
    unsigned* Vs = smem + 4608;          // 4352 words (stride 68)
    unsigned* Ps = smem + 8960;          // 4352 words (Q staging, then P tiles)
    const unsigned smem_u = (unsigned)__cvta_generic_to_shared(smem);
    const unsigned Ks_u = smem_u;
    const unsigned Vs_u = smem_u + 4608 * 4;
    const unsigned Ps_u = smem_u + 8960 * 4;

    const int tid  = threadIdx.x;
    const int warp = tid >> 5, lane = tid & 31;
    const int g = lane >> 2, t = lane & 3;
    const int bh = blockIdx.x;
    const int b = bh >> 4, h = bh & 15;
    const int q0 = blockIdx.y * 64;

    const size_t base = (size_t)b * SS * EE + (size_t)h * HD;

    // staging thread constants: rows r0 + 8i (i=0..7), 16B chunk c4
    const int r0 = tid >> 4;         // 0..7
    const int c4 = tid & 15;         // 0..15
    const unsigned dstW  = (unsigned)((r0 * ASTR + c4 * 4) * 4);  // V/Q chunks
    const unsigned dstWK = (unsigned)((r0 * KSTR + c4 * 4) * 4);  // K chunks

    const float* qsrc = g_q + base + (size_t)(q0 + r0) * EE + c4 * 4;
    const float* ksrc = g_k + base + (size_t)r0 * EE + c4 * 4;
    const float* vsrc = g_v + base + (size_t)r0 * EE + c4 * 4;

    // ---- prologue: Q -> Ps (group1), K0 -> Ks (group2), V0 -> Vs (group3)
    #pragma unroll
    for (int i = 0; i < 8; i++)
        cpa16(Ps_u + dstW + i * 8 * ASTR * 4, qsrc + (size_t)i * 8 * EE);
    cp_commit();
    #pragma unroll
    for (int i = 0; i < 8; i++)
        cpa16(Ks_u + dstWK + i * 8 * KSTR * 4, ksrc + (size_t)i * 8 * EE);
    cp_commit();
    #pragma unroll
    for (int i = 0; i < 8; i++)
        cpa16(Vs_u + dstW + i * 8 * ASTR * 4, vsrc + (size_t)i * 8 * EE);
    cp_commit();

    cp_wait2();          // Q arrived; K0, V0 still pending
    __syncthreads();

    // pull Q A-fragments (warp-local rows), fold SCALE (power of 2: exact)
    unsigned qf[8][4];
    {
        const int m = warp * 16;
        #pragma unroll
        for (int ks = 0; ks < 8; ks++) {
            qf[ks][0] = Ps[(m + g)     * ASTR + ks * 8 + t];
            qf[ks][1] = Ps[(m + g + 8) * ASTR + ks * 8 + t];
            qf[ks][2] = Ps[(m + g)     * ASTR + ks * 8 + t + 4];
            qf[ks][3] = Ps[(m + g + 8) * ASTR + ks * 8 + t + 4];
            #pragma unroll
            for (int j = 0; j < 4; j++)
                qf[ks][j] = __float_as_uint(__uint_as_float(qf[ks][j]) * SCALE);
        }
    }

    float o[8][4] = {};
    float mrow0 = -1e30f, mrow1 = -1e30f, lrow0 = 0.f, lrow1 = 0.f;

    const int NT = SS / 64;
    for (int kt = 0; kt < NT; kt++) {
        // ---- K[kt] ready (V[kt] may still be in flight)
        cp_wait1();
        __syncthreads();

        // ---- S = Q @ K^T  (per warp: 16 x 64); B-fragments via LDS.64
        float s[8][4] = {};
        #pragma unroll
        for (int ks = 0; ks < 8; ks++) {
            #pragma unroll
            for (int ni = 0; ni < 8; ni++) {
                const int n = ni * 8 + g;                 // kv index
                uint2 bv = *(const uint2*)(Ks + n * KSTR + ks * 8 + 2 * t);
                unsigned bb[2] = { bv.x, bv.y };
                mma_tf32(s[ni], qf[ks], bb);
            }
        }

        // ---- online softmax (rows g and g+8; reduce over the 4 lanes of t)
        float mx0 = -1e30f, mx1 = -1e30f;
        #pragma unroll
        for (int ni = 0; ni < 8; ni++) {
            mx0 = fmaxf(mx0, fmaxf(s[ni][0], s[ni][1]));
            mx1 = fmaxf(mx1, fmaxf(s[ni][2], s[ni][3]));
        }
        mx0 = fmaxf(mx0, __shfl_xor_sync(0xffffffffu, mx0, 1));
        mx0 = fmaxf(mx0, __shfl_xor_sync(0xffffffffu, mx0, 2));
        mx1 = fmaxf(mx1, __shfl_xor_sync(0xffffffffu, mx1, 1));
        mx1 = fmaxf(mx1, __shfl_xor_sync(0xffffffffu, mx1, 2));

        float mn0 = fmaxf(mrow0, mx0), mn1 = fmaxf(mrow1, mx1);
        float c0 = __expf(mrow0 - mn0), c1 = __expf(mrow1 - mn1);
        float sum0 = 0.f, sum1 = 0.f;
        #pragma unroll
        for (int ni = 0; ni < 8; ni++) {
            s[ni][0] = __expf(s[ni][0] - mn0);
            s[ni][1] = __expf(s[ni][1] - mn0);
            s[ni][2] = __expf(s[ni][2] - mn1);
            s[ni][3] = __expf(s[ni][3] - mn1);
            sum0 += s[ni][0] + s[ni][1];
            sum1 += s[ni][2] + s[ni][3];
        }
        sum0 += __shfl_xor_sync(0xffffffffu, sum0, 1);
        sum0 += __shfl_xor_sync(0xffffffffu, sum0, 2);
        sum1 += __shfl_xor_sync(0xffffffffu, sum1, 1);
        sum1 += __shfl_xor_sync(0xffffffffu, sum1, 2);
        lrow0 = lrow0 * c0 + sum0;  mrow0 = mn0;
        lrow1 = lrow1 * c1 + sum1;  mrow1 = mn1;
        #pragma unroll
        for (int ni = 0; ni < 8; ni++) {
            o[ni][0] *= c0; o[ni][1] *= c0;
            o[ni][2] *= c1; o[ni][3] *= c1;
        }

        // ---- all warps done reading Ks; prefetch K[kt+1] (overlaps PV)
        __syncthreads();
        if (kt + 1 < NT) {
            const float* kn = ksrc + (size_t)(kt + 1) * 64 * EE;
            #pragma unroll
            for (int i = 0; i < 8; i++)
                cpa16(Ks_u + dstWK + i * 8 * KSTR * 4, kn + (size_t)i * 8 * EE);
            cp_commit();
            cp_wait1();   // V[kt] arrived (K[kt+1] still pending)
        } else {
            cp_wait0();   // V[kt] arrived
        }
        __syncthreads();

        // ---- write P (tf32) to warp-local rows of Ps
        {
            const int m = warp * 16;
            #pragma unroll
            for (int ni = 0; ni < 8; ni++) {
                uint2 w0 = make_uint2(f2tf(s[ni][0]), f2tf(s[ni][1]));
                uint2 w1 = make_uint2(f2tf(s[ni][2]), f2tf(s[ni][3]));
                *(uint2*)&Ps[(m + g)     * ASTR + ni * 8 + 2 * t] = w0;
                *(uint2*)&Ps[(m + g + 8) * ASTR + ni * 8 + 2 * t] = w1;
            }
        }
        __syncwarp();

        // ---- O += P @ V  (A from Ps, B = Vs[j][d])
        {
            const int m = warp * 16;
            #pragma unroll
            for (int ks = 0; ks < 8; ks++) {
                unsigned af[4];
                af[0] = Ps[(m + g)     * ASTR + ks * 8 + t];
                af[1] = Ps[(m + g + 8) * ASTR + ks * 8 + t];
                af[2] = Ps[(m + g)     * ASTR + ks * 8 + t + 4];
                af[3] = Ps[(m + g + 8) * ASTR + ks * 8 + t + 4];
                #pragma unroll
                for (int ni = 0; ni < 8; ni++) {
                    unsigned bf[2];
                    const int n = ni * 8 + g;             // d index
                    bf[0] = Vs[(ks * 8 + t)     * ASTR + n];
                    bf[1] = Vs[(ks * 8 + t + 4) * ASTR + n];
                    mma_tf32(o[ni], af, bf);
                }
            }
        }
        __syncthreads();   // all warps done reading Vs

        // ---- prefetch V[kt+1] (overlaps next S phase)
        if (kt + 1 < NT) {
            const float* vn = vsrc + (size_t)(kt + 1) * 64 * EE;
            #pragma unroll
            for (int i = 0; i < 8; i++)
                cpa16(Vs_u + dstW + i * 8 * ASTR * 4, vn + (size_t)i * 8 * EE);
            cp_commit();
        }
    }

    // ---- normalize, round to tf32 (consumed by cp.async out_gemm), store
    float inv0 = 1.f / lrow0, inv1 = 1.f / lrow1;
    const int r0q = q0 + warp * 16 + g;
    #pragma unroll
    for (int ni = 0; ni < 8; ni++) {
        const int d = h * HD + ni * 8 + 2 * t;
        float2 w0, w1;
        w0.x = __uint_as_float(f2tf(o[ni][0] * inv0));
        w0.y = __uint_as_float(f2tf(o[ni][1] * inv0));
        w1.x = __uint_as_float(f2tf(o[ni][2] * inv1));
        w1.y = __uint_as_float(f2tf(o[ni][3] * inv1));
        *(float2*)(g_att + (size_t)(b * SS + r0q)     * EE + d) = w0;
        *(float2*)(g_att + (size_t)(b * SS + r0q + 8) * EE + d) = w1;
    }
}

// ---------------------------------------------------------------------------
// Launch
// ---------------------------------------------------------------------------
extern "C" void kernel_launch(void* const* d_in, const int* in_sizes, int n_in,
                              void* d_out, int out_size)
{
    const float* query = (const float*)d_in[0];
    const float* key_  = (const float*)d_in[1];
    const float* value = (const float*)d_in[2];
    const float* Wq = (const float*)d_in[3];
    const float* bq = (const float*)d_in[4];
    const float* Wk = (const float*)d_in[5];
    const float* bk = (const float*)d_in[6];
    const float* Wv = (const float*)d_in[7];
    const float* bv = (const float*)d_in[8];
    const float* Wo = (const float*)d_in[9];
    const float* bo = (const float*)d_in[10];
    float* out = (float*)d_out;

    float *q, *k, *v, *att, *xq, *xk, *xv, *wq, *wk, *wv, *wo;
    cudaGetSymbolAddress((void**)&q,   g_q);
    cudaGetSymbolAddress((void**)&k,   g_k);
    cudaGetSymbolAddress((void**)&v,   g_v);
    cudaGetSymbolAddress((void**)&att, g_att);
    cudaGetSymbolAddress((void**)&xq,  g_xq);
    cudaGetSymbolAddress((void**)&xk,  g_xk);
    cudaGetSymbolAddress((void**)&xv,  g_xv);
    cudaGetSymbolAddress((void**)&wq,  g_wq);
    cudaGetSymbolAddress((void**)&wk,  g_wk);
    cudaGetSymbolAddress((void**)&wv,  g_wv);
    cudaGetSymbolAddress((void**)&wo,  g_wo);

    static bool attr_done = false;
    if (!attr_done) {
        cudaFuncSetAttribute(qkv_gemm, cudaFuncAttributeMaxDynamicSharedMemorySize, 3 * STGB);
        cudaFuncSetAttribute(out_gemm, cudaFuncAttributeMaxDynamicSharedMemorySize, 3 * STGB);
        cudaFuncSetAttribute(attn_tc,  cudaFuncAttributeMaxDynamicSharedMemorySize, ATT_SMEM_W * 4);
        attr_done = true;
    }

    // 1) prepass: round inputs + weights to tf32
    RoundArgs ra;
    ra.src[0] = query; ra.dst[0] = xq; ra.n4[0] = MTOT * EE / 4;
    ra.src[1] = key_;  ra.dst[1] = xk; ra.n4[1] = MTOT * EE / 4;
    ra.src[2] = value; ra.dst[2] = xv; ra.n4[2] = MTOT * EE / 4;
    ra.src[3] = Wq;    ra.dst[3] = wq; ra.n4[3] = EE * EE / 4;
    ra.src[4] = Wk;    ra.dst[4] = wk; ra.n4[4] = EE * EE / 4;
    ra.src[5] = Wv;    ra.dst[5] = wv; ra.n4[5] = EE * EE / 4;
    ra.src[6] = Wo;    ra.dst[6] = wo; ra.n4[6] = EE * EE / 4;
    tf32_round<<<dim3(1024, 7), 256>>>(ra);

    // 2) QKV projections (K stored pair-permuted)
    QKVArgs args;
    args.A[0] = xq; args.A[1] = xk; args.A[2] = xv;
    args.W[0] = wq; args.W[1] = wk; args.W[2] = wv;
    args.bias[0] = bq; args.bias[1] = bk; args.bias[2] = bv;
    args.C[0] = q; args.C[1] = k; args.C[2] = v;
    qkv_gemm<<<dim3(EE / 128, MTOT / 128, 3), 256, 3 * STGB>>>(args);

    // 3) attention
    attn_tc<<<dim3(BB * HH, SS / 64), 128, ATT_SMEM_W * 4>>>();

    // 4) output projection
    out_gemm<<<dim3(EE / 128, MTOT / 128), 256, 3 * STGB>>>(att, wo, bo, out);
}

// round 11
// speedup vs baseline: 1.2160x; 1.1156x over previous
#include <cuda_runtime.h>
#include <math.h>

#define BB 2
#define SS 2048
#define EE 1024
#define HH 16
#define HD 64
#define MTOT (BB*SS)
#define SCALE 0.125f                    // 1/sqrt(64)
#define SCALEL 0.1803368801111204f      // 0.125 * log2(e)

// Scratch (allocation-free rule): device globals
__device__ float g_q[MTOT * EE];     // tf32-rounded Q projection
__device__ float g_k[MTOT * EE];     // tf32-rounded K, PAIR-PERMUTED cols
__device__ float g_v[MTOT * EE];     // tf32-rounded V, TRANSPOSED [b*1024+h*64+d][s], s pair-permuted
__device__ float g_att[MTOT * EE];   // tf32-rounded attention output
__device__ float g_xq[MTOT * EE];    // tf32-rounded inputs
__device__ float g_xk[MTOT * EE];
__device__ float g_xv[MTOT * EE];
__device__ float g_wq[EE * EE];      // tf32-rounded weights
__device__ float g_wk[EE * EE];
__device__ float g_wv[EE * EE];
__device__ float g_wo[EE * EE];

// ---------------------------------------------------------------------------
// helpers
// ---------------------------------------------------------------------------
__device__ __forceinline__ unsigned f2tf(float f) {
    unsigned r;
    asm("cvt.rna.tf32.f32 %0, %1;" : "=r"(r) : "f"(f));
    return r;
}

__device__ __forceinline__ float ex2(float x) {
    float r;
    asm("ex2.approx.f32 %0, %1;" : "=f"(r) : "f"(x));
    return r;
}

__device__ __forceinline__ void mma_tf32(float c[4], const unsigned a[4], const unsigned b[2]) {
    asm volatile(
        "mma.sync.aligned.m16n8k8.row.col.f32.tf32.tf32.f32 "
        "{%0,%1,%2,%3}, {%4,%5,%6,%7}, {%8,%9}, {%0,%1,%2,%3};"
        : "+f"(c[0]), "+f"(c[1]), "+f"(c[2]), "+f"(c[3])
        : "r"(a[0]), "r"(a[1]), "r"(a[2]), "r"(a[3]), "r"(b[0]), "r"(b[1]));
}

__device__ __forceinline__ void cpa16(unsigned dst, const void* src) {
    asm volatile("cp.async.cg.shared.global [%0], [%1], 16;" :: "r"(dst), "l"(src) : "memory");
}
__device__ __forceinline__ void cp_commit() { asm volatile("cp.async.commit_group;" ::: "memory"); }
__device__ __forceinline__ void cp_wait0() { asm volatile("cp.async.wait_group 0;" ::: "memory"); }
__device__ __forceinline__ void cp_wait1() { asm volatile("cp.async.wait_group 1;" ::: "memory"); }
__device__ __forceinline__ void cp_wait2() { asm volatile("cp.async.wait_group 2;" ::: "memory"); }

// ---------------------------------------------------------------------------
// Prepass: round 7 tensors to tf32 copies
// ---------------------------------------------------------------------------
struct RoundArgs {
    const float* src[7];
    float*       dst[7];
    int          n4[7];
};

__global__ __launch_bounds__(256) void tf32_round(RoundArgs a) {
    const int z = blockIdx.y;
    const int n4 = a.n4[z];
    const float4* s = (const float4*)a.src[z];
    float4* d = (float4*)a.dst[z];
    for (int i = blockIdx.x * blockDim.x + threadIdx.x; i < n4;
         i += gridDim.x * blockDim.x) {
        float4 v = s[i];
        v.x = __uint_as_float(f2tf(v.x));
        v.y = __uint_as_float(f2tf(v.y));
        v.z = __uint_as_float(f2tf(v.z));
        v.w = __uint_as_float(f2tf(v.w));
        d[i] = v;
    }
}

// ---------------------------------------------------------------------------
// GEMM: C[M,N] = A[M,K] @ W[N,K]^T + bias   (A, W pre-rounded tf32)
// R2 compute loop + cp.async 3-stage staging (R6 WIN).
// PERM=1 (K): pair-permute cols within 8-groups -> attention LDS.64 B-frags.
// PERM=2 (V): store transposed [b*1024+n][s] with s pair-permuted.
// ---------------------------------------------------------------------------
#define GSTR 36
#define STGW 9216            // words per stage: A 128*36, B 128*36
#define STGB (STGW * 4)      // bytes per stage

struct QKVArgs {
    const float* A[3];
    const float* W[3];
    const float* bias[3];
    float*       C[3];
};

template<bool RND, int PERM>
__device__ __forceinline__ void gemm_body(
    const float* __restrict__ A, const float* __restrict__ W,
    const float* __restrict__ bias, float* __restrict__ C)
{
    extern __shared__ unsigned sm[];   // 3 stages x 9216 words = 108 KB
    const unsigned smem_u = (unsigned)__cvta_generic_to_shared(sm);

    const int tid  = threadIdx.x;
    const int warp = tid >> 5, lane = tid & 31;
    const int g = lane >> 2, t = lane & 3;
    const int wm = warp & 1, wn = warp >> 1;     // 2 x 4 warps, warp tile 64x32
    const int bm = blockIdx.y * 128, bn = blockIdx.x * 128;

    // staging constants: thread covers rows m0+32i (i=0..3), k-quad kq (16B)
    const int kq = tid & 7;          // fixed k-quad
    const int m0 = tid >> 3;         // 0..31
    const float* Asrc = A + (size_t)(bm + m0) * EE + kq * 4;
    const float* Wsrc = W + (size_t)(bn + m0) * EE + kq * 4;
    const unsigned dA = smem_u + (m0 * GSTR + kq * 4) * 4;  // + i*4608B + stage*STGB
    const unsigned dB = dA + 4608 * 4;                      // B block at word 4608

    float acc[4][4][4] = {};
    const int NK = EE / 32;          // 32

    // prologue: stage tiles 0 and 1
    #pragma unroll
    for (int p = 0; p < 2; p++) {
        const unsigned so = p * STGB;
        const int ko = p * 32;
        #pragma unroll
        for (int i = 0; i < 4; i++) {
            cpa16(dA + so + i * 4608, Asrc + ko + (size_t)i * 32 * EE);
            cpa16(dB + so + i * 4608, Wsrc + ko + (size_t)i * 32 * EE);
        }
        cp_commit();
    }

    int st = 0;   // stage holding tile kt
    for (int kt = 0; kt < NK; kt++) {
        if (kt + 1 < NK) cp_wait1(); else cp_wait0();
        __syncthreads();

        // prefetch tile kt+2 into stage (st+2)%3 (its readers done at kt-1)
        if (kt + 2 < NK) {
            const int s2 = (st + 2 >= 3) ? st - 1 : st + 2;
            const unsigned so = s2 * STGB;
            const int ko = (kt + 2) * 32;
            #pragma unroll
            for (int i = 0; i < 4; i++) {
                cpa16(dA + so + i * 4608, Asrc + ko + (size_t)i * 32 * EE);
                cpa16(dB + so + i * 4608, Wsrc + ko + (size_t)i * 32 * EE);
            }
            cp_commit();
        }

        // ---- R2 compute loop: 4 k-steps of 8
        const unsigned* Asm = sm + st * STGW;
        const unsigned* Bsm = Asm + 4608;
        #pragma unroll
        for (int ksc = 0; ksc < 4; ksc++) {
            unsigned af[4][4], bf[4][2];
            #pragma unroll
            for (int mi = 0; mi < 4; mi++) {
                const int row = wm * 64 + mi * 16;
                af[mi][0] = Asm[(row + g)     * GSTR + ksc * 8 + t];
                af[mi][1] = Asm[(row + g + 8) * GSTR + ksc * 8 + t];
                af[mi][2] = Asm[(row + g)     * GSTR + ksc * 8 + t + 4];
                af[mi][3] = Asm[(row + g + 8) * GSTR + ksc * 8 + t + 4];
            }
            #pragma unroll
            for (int ni = 0; ni < 4; ni++) {
                const int col = wn * 32 + ni * 8 + g;
                bf[ni][0] = Bsm[col * GSTR + ksc * 8 + t];
                bf[ni][1] = Bsm[col * GSTR + ksc * 8 + t + 4];
            }
            #pragma unroll
            for (int mi = 0; mi < 4; mi++)
                #pragma unroll
                for (int ni = 0; ni < 4; ni++)
                    mma_tf32(acc[mi][ni], af[mi], bf[ni]);
        }
        st = (st + 1 >= 3) ? 0 : st + 1;
    }

    // ---- epilogue: add bias (fp32), optional tf32 round, store
    #pragma unroll
    for (int mi = 0; mi < 4; mi++) {
        #pragma unroll
        for (int r2 = 0; r2 < 2; r2++) {
            const int m = bm + wm * 64 + mi * 16 + g + r2 * 8;
            #pragma unroll
            for (int ni = 0; ni < 4; ni++) {
                const int n = bn + wn * 32 + ni * 8 + 2 * t;
                float2 bv = *(const float2*)(bias + n);
                float2 o;
                o.x = acc[mi][ni][r2 * 2 + 0] + bv.x;
                o.y = acc[mi][ni][r2 * 2 + 1] + bv.y;
                if (RND) {
                    o.x = __uint_as_float(f2tf(o.x));
                    o.y = __uint_as_float(f2tf(o.y));
                }
                if (PERM == 1) {
                    // K: pair-permute cols within 8-group: pos(j)=(j%4)*2+j/4
                    const int jj = n & 7;                         // = 2t
                    const int p0 = ((jj & 3) << 1) + (jj >> 2);
                    float* dst = C + (size_t)m * EE + (n & ~7);
                    dst[p0]     = o.x;
                    dst[p0 + 2] = o.y;
                } else if (PERM == 2) {
                    // V: transpose to [b*1024+n][s], s pair-permuted in 8-groups
                    const int bI = m >> 11;
                    const int sI = m & 2047;                      // sI & 7 == g
                    const int scol = (sI & ~7) + ((sI & 3) << 1) + ((sI & 7) >> 2);
                    float* dst = C + (size_t)(bI * 1024 + n) * SS + scol;
                    dst[0]  = o.x;    // row n   (d)
                    dst[SS] = o.y;    // row n+1 (d+1)
                } else {
                    *(float2*)(C + (size_t)m * EE + n) = o;
                }
            }
        }
    }
}

__global__ __launch_bounds__(256, 2) void qkv_gemm(QKVArgs args) {
    const int z = blockIdx.z;
    if (z == 0)
        gemm_body<true, 0>(args.A[0], args.W[0], args.bias[0], args.C[0]);
    else if (z == 1)
        gemm_body<true, 1>(args.A[1], args.W[1], args.bias[1], args.C[1]);
    else
        gemm_body<true, 2>(args.A[2], args.W[2], args.bias[2], args.C[2]);
}

__global__ __launch_bounds__(256, 2) void out_gemm(const float* __restrict__ A,
                                                   const float* __restrict__ W,
                                                   const float* __restrict__ bias,
                                                   float* __restrict__ C) {
    gemm_body<false, 0>(A, W, bias, C);
}

// ---------------------------------------------------------------------------
// Flash attention, tf32 mma, cp.async pipelined staging (R7/R8 base).
// Block = (b, h, 64 q-rows), 128 threads (4 warps, 16 rows each), 4 CTAs/SM.
// R10: K pair-permuted -> S-phase B-frags via LDS.64 (stride 72).
// R11: V transposed+permuted in GMEM -> PV B-frags via LDS.64 (stride 72);
//      softmax in log2 domain (Q pre-scaled by 0.125*log2e, raw EX2).
// ---------------------------------------------------------------------------
#define ASTR 68
#define KSTR 72
// smem words: Ks 64*72=4608 | Vt 64*72=4608 | Ps 64*68=4352 -> 13568 (53 KB)
#define ATT_SMEM_W 13568

__global__ __launch_bounds__(128, 4) void attn_tc() {
    extern __shared__ unsigned smem[];
    unsigned* Ks = smem;                 // 4608 words (stride 72)
    unsigned* Vt = smem + 4608;          // 4608 words (stride 72, [d][kv_perm])
    unsigned* Ps = smem + 9216;          // 4352 words (Q staging, then P tiles)
    const unsigned smem_u = (unsigned)__cvta_generic_to_shared(smem);
    const unsigned Ks_u = smem_u;
    const unsigned Vt_u = smem_u + 4608 * 4;
    const unsigned Ps_u = smem_u + 9216 * 4;

    const int tid  = threadIdx.x;
    const int warp = tid >> 5, lane = tid & 31;
    const int g = lane >> 2, t = lane & 3;
    const int bh = blockIdx.x;
    const int b = bh >> 4, h = bh & 15;
    const int q0 = blockIdx.y * 64;

    const size_t base = (size_t)b * SS * EE + (size_t)h * HD;

    // staging thread constants: rows r0 + 8i (i=0..7), 16B chunk c4
    const int r0 = tid >> 4;         // 0..7
    const int c4 = tid & 15;         // 0..15
    const unsigned dstW  = (unsigned)((r0 * ASTR + c4 * 4) * 4);  // Q chunks
    const unsigned dstWK = (unsigned)((r0 * KSTR + c4 * 4) * 4);  // K/V chunks

    const float* qsrc = g_q + base + (size_t)(q0 + r0) * EE + c4 * 4;
    const float* ksrc = g_k + base + (size_t)r0 * EE + c4 * 4;
    // V transposed: rows = b*1024 + h*64 + d, cols = s (pair-permuted)
    const float* vsrc = g_v + (size_t)(b * 1024 + h * HD + r0) * SS + c4 * 4;

    // ---- prologue: Q -> Ps (group1), K0 -> Ks (group2), V0 -> Vt (group3)
    #pragma unroll
    for (int i = 0; i < 8; i++)
        cpa16(Ps_u + dstW + i * 8 * ASTR * 4, qsrc + (size_t)i * 8 * EE);
    cp_commit();
    #pragma unroll
    for (int i = 0; i < 8; i++)
        cpa16(Ks_u + dstWK + i * 8 * KSTR * 4, ksrc + (size_t)i * 8 * EE);
    cp_commit();
    #pragma unroll
    for (int i = 0; i < 8; i++)
        cpa16(Vt_u + dstWK + i * 8 * KSTR * 4, vsrc + (size_t)i * 8 * SS);
    cp_commit();

    cp_wait2();          // Q arrived; K0, V0 still pending
    __syncthreads();

    // pull Q A-fragments, fold 0.125*log2(e) (re-rounded to tf32)
    unsigned qf[8][4];
    {
        const int m = warp * 16;
        #pragma unroll
        for (int ks = 0; ks < 8; ks++) {
            qf[ks][0] = Ps[(m + g)     * ASTR + ks * 8 + t];
            qf[ks][1] = Ps[(m + g + 8) * ASTR + ks * 8 + t];
            qf[ks][2] = Ps[(m + g)     * ASTR + ks * 8 + t + 4];
            qf[ks][3] = Ps[(m + g + 8) * ASTR + ks * 8 + t + 4];
            #pragma unroll
            for (int j = 0; j < 4; j++)
                qf[ks][j] = f2tf(__uint_as_float(qf[ks][j]) * SCALEL);
        }
    }

    float o[8][4] = {};
    float mrow0 = -1e30f, mrow1 = -1e30f, lrow0 = 0.f, lrow1 = 0.f;

    const int NT = SS / 64;
    for (int kt = 0; kt < NT; kt++) {
        // ---- K[kt] ready (V[kt] may still be in flight)
        cp_wait1();
        __syncthreads();

        // ---- S = Q @ K^T  (log2-domain); B-fragments via LDS.64
        float s[8][4] = {};
        #pragma unroll
        for (int ks = 0; ks < 8; ks++) {
            #pragma unroll
            for (int ni = 0; ni < 8; ni++) {
                const int n = ni * 8 + g;                 // kv index
                uint2 bv = *(const uint2*)(Ks + n * KSTR + ks * 8 + 2 * t);
                unsigned bb[2] = { bv.x, bv.y };
                mma_tf32(s[ni], qf[ks], bb);
            }
        }

        // ---- online softmax (log2 domain; rows g, g+8; reduce across t)
        float mx0 = -1e30f, mx1 = -1e30f;
        #pragma unroll
        for (int ni = 0; ni < 8; ni++) {
            mx0 = fmaxf(mx0, fmaxf(s[ni][0], s[ni][1]));
            mx1 = fmaxf(mx1, fmaxf(s[ni][2], s[ni][3]));
        }
        mx0 = fmaxf(mx0, __shfl_xor_sync(0xffffffffu, mx0, 1));
        mx0 = fmaxf(mx0, __shfl_xor_sync(0xffffffffu, mx0, 2));
        mx1 = fmaxf(mx1, __shfl_xor_sync(0xffffffffu, mx1, 1));
        mx1 = fmaxf(mx1, __shfl_xor_sync(0xffffffffu, mx1, 2));

        float mn0 = fmaxf(mrow0, mx0), mn1 = fmaxf(mrow1, mx1);
        float c0 = ex2(mrow0 - mn0), c1 = ex2(mrow1 - mn1);
        float sum0 = 0.f, sum1 = 0.f;
        #pragma unroll
        for (int ni = 0; ni < 8; ni++) {
            s[ni][0] = ex2(s[ni][0] - mn0);
            s[ni][1] = ex2(s[ni][1] - mn0);
            s[ni][2] = ex2(s[ni][2] - mn1);
            s[ni][3] = ex2(s[ni][3] - mn1);
            sum0 += s[ni][0] + s[ni][1];
            sum1 += s[ni][2] + s[ni][3];
        }
        sum0 += __shfl_xor_sync(0xffffffffu, sum0, 1);
        sum0 += __shfl_xor_sync(0xffffffffu, sum0, 2);
        sum1 += __shfl_xor_sync(0xffffffffu, sum1, 1);
        sum1 += __shfl_xor_sync(0xffffffffu, sum1, 2);
        lrow0 = lrow0 * c0 + sum0;  mrow0 = mn0;
        lrow1 = lrow1 * c1 + sum1;  mrow1 = mn1;
        #pragma unroll
        for (int ni = 0; ni < 8; ni++) {
            o[ni][0] *= c0; o[ni][1] *= c0;
            o[ni][2] *= c1; o[ni][3] *= c1;
        }

        // ---- all warps done reading Ks; prefetch K[kt+1] (overlaps PV)
        __syncthreads();
        if (kt + 1 < NT) {
            const float* kn = ksrc + (size_t)(kt + 1) * 64 * EE;
            #pragma unroll
            for (int i = 0; i < 8; i++)
                cpa16(Ks_u + dstWK + i * 8 * KSTR * 4, kn + (size_t)i * 8 * EE);
            cp_commit();
            cp_wait1();   // V[kt] arrived (K[kt+1] still pending)
        } else {
            cp_wait0();   // V[kt] arrived
        }
        __syncthreads();

        // ---- write P (tf32) to warp-local rows of Ps
        {
            const int m = warp * 16;
            #pragma unroll
            for (int ni = 0; ni < 8; ni++) {
                uint2 w0 = make_uint2(f2tf(s[ni][0]), f2tf(s[ni][1]));
                uint2 w1 = make_uint2(f2tf(s[ni][2]), f2tf(s[ni][3]));
                *(uint2*)&Ps[(m + g)     * ASTR + ni * 8 + 2 * t] = w0;
                *(uint2*)&Ps[(m + g + 8) * ASTR + ni * 8 + 2 * t] = w1;
            }
        }
        __syncwarp();

        // ---- O += P @ V  (A from Ps, B from Vt via LDS.64)
        {
            const int m = warp * 16;
            #pragma unroll
            for (int ks = 0; ks < 8; ks++) {
                unsigned af[4];
                af[0] = Ps[(m + g)     * ASTR + ks * 8 + t];
                af[1] = Ps[(m + g + 8) * ASTR + ks * 8 + t];
                af[2] = Ps[(m + g)     * ASTR + ks * 8 + t + 4];
                af[3] = Ps[(m + g + 8) * ASTR + ks * 8 + t + 4];
                #pragma unroll
                for (int ni = 0; ni < 8; ni++) {
                    const int n = ni * 8 + g;             // d index
                    uint2 bv = *(const uint2*)(Vt + n * KSTR + ks * 8 + 2 * t);
                    unsigned bb[2] = { bv.x, bv.y };
                    mma_tf32(o[ni], af, bb);
                }
            }
        }
        __syncthreads();   // all warps done reading Vt

        // ---- prefetch V[kt+1] (overlaps next S phase)
        if (kt + 1 < NT) {
            const float* vn = vsrc + (size_t)(kt + 1) * 64;
            #pragma unroll
            for (int i = 0; i < 8; i++)
                cpa16(Vt_u + dstWK + i * 8 * KSTR * 4, vn + (size_t)i * 8 * SS);
            cp_commit();
        }
    }

    // ---- normalize, round to tf32 (consumed by cp.async out_gemm), store
    float inv0 = 1.f / lrow0, inv1 = 1.f / lrow1;
    const int r0q = q0 + warp * 16 + g;
    #pragma unroll
    for (int ni = 0; ni < 8; ni++) {
        const int d = h * HD + ni * 8 + 2 * t;
        float2 w0, w1;
        w0.x = __uint_as_float(f2tf(o[ni][0] * inv0));
        w0.y = __uint_as_float(f2tf(o[ni][1] * inv0));
        w1.x = __uint_as_float(f2tf(o[ni][2] * inv1));
        w1.y = __uint_as_float(f2tf(o[ni][3] * inv1));
        *(float2*)(g_att + (size_t)(b * SS + r0q)     * EE + d) = w0;
        *(float2*)(g_att + (size_t)(b * SS + r0q + 8) * EE + d) = w1;
    }
}

// ---------------------------------------------------------------------------
// Launch
// ---------------------------------------------------------------------------
extern "C" void kernel_launch(void* const* d_in, const int* in_sizes, int n_in,
                              void* d_out, int out_size)
{
    const float* query = (const float*)d_in[0];
    const float* key_  = (const float*)d_in[1];
    const float* value = (const float*)d_in[2];
    const float* Wq = (const float*)d_in[3];
    const float* bq = (const float*)d_in[4];
    const float* Wk = (const float*)d_in[5];
    const float* bk = (const float*)d_in[6];
    const float* Wv = (const float*)d_in[7];
    const float* bv = (const float*)d_in[8];
    const float* Wo = (const float*)d_in[9];
    const float* bo = (const float*)d_in[10];
    float* out = (float*)d_out;

    float *q, *k, *v, *att, *xq, *xk, *xv, *wq, *wk, *wv, *wo;
    cudaGetSymbolAddress((void**)&q,   g_q);
    cudaGetSymbolAddress((void**)&k,   g_k);
    cudaGetSymbolAddress((void**)&v,   g_v);
    cudaGetSymbolAddress((void**)&att, g_att);
    cudaGetSymbolAddress((void**)&xq,  g_xq);
    cudaGetSymbolAddress((void**)&xk,  g_xk);
    cudaGetSymbolAddress((void**)&xv,  g_xv);
    cudaGetSymbolAddress((void**)&wq,  g_wq);
    cudaGetSymbolAddress((void**)&wk,  g_wk);
    cudaGetSymbolAddress((void**)&wv,  g_wv);
    cudaGetSymbolAddress((void**)&wo,  g_wo);

    static bool attr_done = false;
    if (!attr_done) {
        cudaFuncSetAttribute(qkv_gemm, cudaFuncAttributeMaxDynamicSharedMemorySize, 3 * STGB);
        cudaFuncSetAttribute(out_gemm, cudaFuncAttributeMaxDynamicSharedMemorySize, 3 * STGB);
        cudaFuncSetAttribute(attn_tc,  cudaFuncAttributeMaxDynamicSharedMemorySize, ATT_SMEM_W * 4);
        attr_done = true;
    }

    // 1) prepass: round inputs + weights to tf32
    RoundArgs ra;
    ra.src[0] = query; ra.dst[0] = xq; ra.n4[0] = MTOT * EE / 4;
    ra.src[1] = key_;  ra.dst[1] = xk; ra.n4[1] = MTOT * EE / 4;
    ra.src[2] = value; ra.dst[2] = xv; ra.n4[2] = MTOT * EE / 4;
    ra.src[3] = Wq;    ra.dst[3] = wq; ra.n4[3] = EE * EE / 4;
    ra.src[4] = Wk;    ra.dst[4] = wk; ra.n4[4] = EE * EE / 4;
    ra.src[5] = Wv;    ra.dst[5] = wv; ra.n4[5] = EE * EE / 4;
    ra.src[6] = Wo;    ra.dst[6] = wo; ra.n4[6] = EE * EE / 4;
    tf32_round<<<dim3(1024, 7), 256>>>(ra);

    // 2) QKV projections (K pair-permuted; V transposed+permuted)
    QKVArgs args;
    args.A[0] = xq; args.A[1] = xk; args.A[2] = xv;
    args.W[0] = wq; args.W[1] = wk; args.W[2] = wv;
    args.bias[0] = bq; args.bias[1] = bk; args.bias[2] = bv;
    args.C[0] = q; args.C[1] = k; args.C[2] = v;
    qkv_gemm<<<dim3(EE / 128, MTOT / 128, 3), 256, 3 * STGB>>>(args);

    // 3) attention
    attn_tc<<<dim3(BB * HH, SS / 64), 128, ATT_SMEM_W * 4>>>();

    // 4) output projection
    out_gemm<<<dim3(EE / 128, MTOT / 128), 256, 3 * STGB>>>(att, wo, bo, out);
}

// round 12
// speedup vs baseline: 1.2975x; 1.0670x over previous
#include <cuda_runtime.h>
#include <math.h>

#define BB 2
#define SS 2048
#define EE 1024
#define HH 16
#define HD 64
#define MTOT (BB*SS)
#define SCALEL 0.1803368801111204f      // 0.125 * log2(e)

// Scratch (allocation-free rule): device globals
// K-dim pair-permute (within 8-groups, pos(j)=(j%4)*2+j/4) applied to:
//   g_xq/g_xk/g_xv, g_wq/g_wk/g_wv/g_wo (prepass), g_att (attention epilogue)
__device__ float g_q[MTOT * EE];     // Q projection (normal layout)
__device__ float g_k[MTOT * EE];     // K projection, pair-permuted N cols (R10)
__device__ float g_v[MTOT * EE];     // V transposed [b*1024+h*64+d][s], s pair-permuted (R11)
__device__ float g_att[MTOT * EE];   // attention out, pair-permuted K cols (R12)
__device__ float g_xq[MTOT * EE];
__device__ float g_xk[MTOT * EE];
__device__ float g_xv[MTOT * EE];
__device__ float g_wq[EE * EE];
__device__ float g_wk[EE * EE];
__device__ float g_wv[EE * EE];
__device__ float g_wo[EE * EE];

// ---------------------------------------------------------------------------
// helpers
// ---------------------------------------------------------------------------
__device__ __forceinline__ unsigned f2tf(float f) {
    unsigned r;
    asm("cvt.rna.tf32.f32 %0, %1;" : "=r"(r) : "f"(f));
    return r;
}

__device__ __forceinline__ float ex2(float x) {
    float r;
    asm("ex2.approx.f32 %0, %1;" : "=f"(r) : "f"(x));
    return r;
}

__device__ __forceinline__ void mma_tf32(float c[4], const unsigned a[4], const unsigned b[2]) {
    asm volatile(
        "mma.sync.aligned.m16n8k8.row.col.f32.tf32.tf32.f32 "
        "{%0,%1,%2,%3}, {%4,%5,%6,%7}, {%8,%9}, {%0,%1,%2,%3};"
        : "+f"(c[0]), "+f"(c[1]), "+f"(c[2]), "+f"(c[3])
        : "r"(a[0]), "r"(a[1]), "r"(a[2]), "r"(a[3]), "r"(b[0]), "r"(b[1]));
}

__device__ __forceinline__ void cpa16(unsigned dst, const void* src) {
    asm volatile("cp.async.cg.shared.global [%0], [%1], 16;" :: "r"(dst), "l"(src) : "memory");
}
__device__ __forceinline__ void cp_commit() { asm volatile("cp.async.commit_group;" ::: "memory"); }
__device__ __forceinline__ void cp_wait0() { asm volatile("cp.async.wait_group 0;" ::: "memory"); }
__device__ __forceinline__ void cp_wait1() { asm volatile("cp.async.wait_group 1;" ::: "memory"); }
__device__ __forceinline__ void cp_wait2() { asm volatile("cp.async.wait_group 2;" ::: "memory"); }

// ---------------------------------------------------------------------------
// Prepass: round 7 tensors to tf32 AND pair-permute K-dim within 8-groups
// pos(j) = (j%4)*2 + j/4  -> chunk j0..j0+3 goes to base + off + {0,2,4,6},
// off = (chunk index & 1)
// ---------------------------------------------------------------------------
struct RoundArgs {
    const float* src[7];
    float*       dst[7];
    int          n4[7];
};

__global__ __launch_bounds__(256) void tf32_round(RoundArgs a) {
    const int z = blockIdx.y;
    const int n4 = a.n4[z];
    const float4* s = (const float4*)a.src[z];
    float* dst = a.dst[z];
    for (int i = blockIdx.x * blockDim.x + threadIdx.x; i < n4;
         i += gridDim.x * blockDim.x) {
        float4 v = s[i];
        float* db = dst + (((size_t)i & ~(size_t)1) << 2);  // group base
        const int off = i & 1;
        db[off + 0] = __uint_as_float(f2tf(v.x));
        db[off + 2] = __uint_as_float(f2tf(v.y));
        db[off + 4] = __uint_as_float(f2tf(v.z));
        db[off + 6] = __uint_as_float(f2tf(v.w));
    }
}

// ---------------------------------------------------------------------------
// GEMM: C[M,N] = A[M,K] @ W[N,K]^T + bias   (A, W tf32 + K-pair-permuted)
// CTA 128x128x32, 256 threads (8 warps 2Mx4N), warp tile 64x32.
// R12: smem stride 40 (==8 mod 32 -> conflict-free LDS.64 per 16-lane phase),
// all fragments via LDS.64; 2-stage cp.async pipeline (80 KB, 2 CTAs/SM).
// Out-PERM: 1 = pair-permute output N cols (K proj); 2 = transpose+permute (V).
// ---------------------------------------------------------------------------
#define GSTR 40
#define STG2W (128 * GSTR * 2)   // 10240 words per stage (A block then B block)
#define STG2B (STG2W * 4)

struct QKVArgs {
    const float* A[3];
    const float* W[3];
    const float* bias[3];
    float*       C[3];
};

template<bool RND, int PERM>
__device__ __forceinline__ void gemm_body(
    const float* __restrict__ A, const float* __restrict__ W,
    const float* __restrict__ bias, float* __restrict__ C)
{
    extern __shared__ unsigned sm[];   // 2 stages x 10240 words = 80 KB
    const unsigned smem_u = (unsigned)__cvta_generic_to_shared(sm);

    const int tid  = threadIdx.x;
    const int warp = tid >> 5, lane = tid & 31;
    const int g = lane >> 2, t = lane & 3;
    const int wm = warp & 1, wn = warp >> 1;     // 2 x 4 warps, warp tile 64x32
    const int bm = blockIdx.y * 128, bn = blockIdx.x * 128;

    // staging: thread covers rows m0+32i (i=0..3), k-quad kq (16B chunks)
    const int kq = tid & 7;
    const int m0 = tid >> 3;
    const float* Asrc = A + (size_t)(bm + m0) * EE + kq * 4;
    const float* Wsrc = W + (size_t)(bn + m0) * EE + kq * 4;
    const unsigned dA = smem_u + (m0 * GSTR + kq * 4) * 4;   // + i*(32*GSTR*4) + stage*STG2B
    const unsigned dB = dA + 128 * GSTR * 4;

    float acc[4][4][4] = {};
    const int NK = EE / 32;          // 32

    // prologue: stage tiles 0 and 1
    #pragma unroll
    for (int p = 0; p < 2; p++) {
        const unsigned so = p * STG2B;
        const int ko = p * 32;
        #pragma unroll
        for (int i = 0; i < 4; i++) {
            cpa16(dA + so + i * (32 * GSTR * 4), Asrc + ko + (size_t)i * 32 * EE);
            cpa16(dB + so + i * (32 * GSTR * 4), Wsrc + ko + (size_t)i * 32 * EE);
        }
        cp_commit();
    }

    for (int kt = 0; kt < NK; kt++) {
        if (kt + 1 < NK) cp_wait1(); else cp_wait0();
        __syncthreads();

        const unsigned* Asm = sm + (kt & 1) * STG2W;
        const unsigned* Bsm = Asm + 128 * GSTR;

        #pragma unroll
        for (int ksc = 0; ksc < 4; ksc++) {
            const int koff = ksc * 8 + 2 * t;
            unsigned af[4][4], bf[4][2];
            #pragma unroll
            for (int mi = 0; mi < 4; mi++) {
                const int row = wm * 64 + mi * 16;
                uint2 a0 = *(const uint2*)(Asm + (row + g)     * GSTR + koff);
                uint2 a1 = *(const uint2*)(Asm + (row + g + 8) * GSTR + koff);
                af[mi][0] = a0.x; af[mi][1] = a1.x; af[mi][2] = a0.y; af[mi][3] = a1.y;
            }
            #pragma unroll
            for (int ni = 0; ni < 4; ni++) {
                const int col = wn * 32 + ni * 8 + g;
                uint2 bv = *(const uint2*)(Bsm + col * GSTR + koff);
                bf[ni][0] = bv.x; bf[ni][1] = bv.y;
            }
            #pragma unroll
            for (int mi = 0; mi < 4; mi++)
                #pragma unroll
                for (int ni = 0; ni < 4; ni++)
                    mma_tf32(acc[mi][ni], af[mi], bf[ni]);
        }
        __syncthreads();

        // prefetch tile kt+2 into the stage just consumed
        if (kt + 2 < NK) {
            const unsigned so = (kt & 1) * STG2B;
            const int ko = (kt + 2) * 32;
            #pragma unroll
            for (int i = 0; i < 4; i++) {
                cpa16(dA + so + i * (32 * GSTR * 4), Asrc + ko + (size_t)i * 32 * EE);
                cpa16(dB + so + i * (32 * GSTR * 4), Wsrc + ko + (size_t)i * 32 * EE);
            }
            cp_commit();
        }
    }

    // ---- epilogue
    #pragma unroll
    for (int mi = 0; mi < 4; mi++) {
        #pragma unroll
        for (int r2 = 0; r2 < 2; r2++) {
            const int m = bm + wm * 64 + mi * 16 + g + r2 * 8;
            #pragma unroll
            for (int ni = 0; ni < 4; ni++) {
                const int n = bn + wn * 32 + ni * 8 + 2 * t;
                float2 bv = *(const float2*)(bias + n);
                float2 o;
                o.x = acc[mi][ni][r2 * 2 + 0] + bv.x;
                o.y = acc[mi][ni][r2 * 2 + 1] + bv.y;
                if (RND) {
                    o.x = __uint_as_float(f2tf(o.x));
                    o.y = __uint_as_float(f2tf(o.y));
                }
                if (PERM == 1) {
                    // K: pair-permute output cols within 8-group
                    const int jj = n & 7;
                    const int p0 = ((jj & 3) << 1) + (jj >> 2);
                    float* dst = C + (size_t)m * EE + (n & ~7);
                    dst[p0]     = o.x;
                    dst[p0 + 2] = o.y;
                } else if (PERM == 2) {
                    // V: transpose to [b*1024+n][s], s pair-permuted in 8-groups
                    const int bI = m >> 11;
                    const int sI = m & 2047;
                    const int scol = (sI & ~7) + ((sI & 3) << 1) + ((sI & 7) >> 2);
                    float* dst = C + (size_t)(bI * 1024 + n) * SS + scol;
                    dst[0]  = o.x;
                    dst[SS] = o.y;
                } else {
                    *(float2*)(C + (size_t)m * EE + n) = o;
                }
            }
        }
    }
}

__global__ __launch_bounds__(256, 2) void qkv_gemm(QKVArgs args) {
    const int z = blockIdx.z;
    if (z == 0)
        gemm_body<true, 0>(args.A[0], args.W[0], args.bias[0], args.C[0]);
    else if (z == 1)
        gemm_body<true, 1>(args.A[1], args.W[1], args.bias[1], args.C[1]);
    else
        gemm_body<true, 2>(args.A[2], args.W[2], args.bias[2], args.C[2]);
}

__global__ __launch_bounds__(256, 2) void out_gemm(const float* __restrict__ A,
                                                   const float* __restrict__ W,
                                                   const float* __restrict__ bias,
                                                   float* __restrict__ C) {
    gemm_body<false, 0>(A, W, bias, C);
}

// ---------------------------------------------------------------------------
// Flash attention, tf32 mma, cp.async pipelined staging (R7/R8 base).
// Block = (b, h, 64 q-rows), 128 threads (4 warps, 16 rows each), 4 CTAs/SM.
// R10: K pair-permuted -> S-phase B-frags via LDS.64 (stride 72).
// R11: V transposed+permuted -> PV B-frags via LDS.64; log2-domain softmax.
// R12: epilogue stores g_att with K-pair-permuted cols (for out_gemm LDS.64).
// ---------------------------------------------------------------------------
#define ASTR 68
#define KSTR 72
// smem words: Ks 64*72=4608 | Vt 64*72=4608 | Ps 64*68=4352 -> 13568 (53 KB)
#define ATT_SMEM_W 13568

__global__ __launch_bounds__(128, 4) void attn_tc() {
    extern __shared__ unsigned smem[];
    unsigned* Ks = smem;                 // 4608 words (stride 72)
    unsigned* Vt = smem + 4608;          // 4608 words (stride 72, [d][kv_perm])
    unsigned* Ps = smem + 9216;          // 4352 words (Q staging, then P tiles)
    const unsigned smem_u = (unsigned)__cvta_generic_to_shared(smem);
    const unsigned Ks_u = smem_u;
    const unsigned Vt_u = smem_u + 4608 * 4;
    const unsigned Ps_u = smem_u + 9216 * 4;

    const int tid  = threadIdx.x;
    const int warp = tid >> 5, lane = tid & 31;
    const int g = lane >> 2, t = lane & 3;
    const int bh = blockIdx.x;
    const int b = bh >> 4, h = bh & 15;
    const int q0 = blockIdx.y * 64;

    const size_t base = (size_t)b * SS * EE + (size_t)h * HD;

    // staging thread constants: rows r0 + 8i (i=0..7), 16B chunk c4
    const int r0 = tid >> 4;
    const int c4 = tid & 15;
    const unsigned dstW  = (unsigned)((r0 * ASTR + c4 * 4) * 4);
    const unsigned dstWK = (unsigned)((r0 * KSTR + c4 * 4) * 4);

    const float* qsrc = g_q + base + (size_t)(q0 + r0) * EE + c4 * 4;
    const float* ksrc = g_k + base + (size_t)r0 * EE + c4 * 4;
    const float* vsrc = g_v + (size_t)(b * 1024 + h * HD + r0) * SS + c4 * 4;

    // ---- prologue: Q -> Ps (group1), K0 -> Ks (group2), V0 -> Vt (group3)
    #pragma unroll
    for (int i = 0; i < 8; i++)
        cpa16(Ps_u + dstW + i * 8 * ASTR * 4, qsrc + (size_t)i * 8 * EE);
    cp_commit();
    #pragma unroll
    for (int i = 0; i < 8; i++)
        cpa16(Ks_u + dstWK + i * 8 * KSTR * 4, ksrc + (size_t)i * 8 * EE);
    cp_commit();
    #pragma unroll
    for (int i = 0; i < 8; i++)
        cpa16(Vt_u + dstWK + i * 8 * KSTR * 4, vsrc + (size_t)i * 8 * SS);
    cp_commit();

    cp_wait2();
    __syncthreads();

    // pull Q A-fragments, fold 0.125*log2(e) (re-rounded to tf32)
    unsigned qf[8][4];
    {
        const int m = warp * 16;
        #pragma unroll
        for (int ks = 0; ks < 8; ks++) {
            qf[ks][0] = Ps[(m + g)     * ASTR + ks * 8 + t];
            qf[ks][1] = Ps[(m + g + 8) * ASTR + ks * 8 + t];
            qf[ks][2] = Ps[(m + g)     * ASTR + ks * 8 + t + 4];
            qf[ks][3] = Ps[(m + g + 8) * ASTR + ks * 8 + t + 4];
            #pragma unroll
            for (int j = 0; j < 4; j++)
                qf[ks][j] = f2tf(__uint_as_float(qf[ks][j]) * SCALEL);
        }
    }

    float o[8][4] = {};
    float mrow0 = -1e30f, mrow1 = -1e30f, lrow0 = 0.f, lrow1 = 0.f;

    const int NT = SS / 64;
    for (int kt = 0; kt < NT; kt++) {
        cp_wait1();
        __syncthreads();

        // ---- S = Q @ K^T (log2-domain); B-fragments via LDS.64
        float s[8][4] = {};
        #pragma unroll
        for (int ks = 0; ks < 8; ks++) {
            #pragma unroll
            for (int ni = 0; ni < 8; ni++) {
                const int n = ni * 8 + g;
                uint2 bv = *(const uint2*)(Ks + n * KSTR + ks * 8 + 2 * t);
                unsigned bb[2] = { bv.x, bv.y };
                mma_tf32(s[ni], qf[ks], bb);
            }
        }

        // ---- online softmax (log2 domain)
        float mx0 = -1e30f, mx1 = -1e30f;
        #pragma unroll
        for (int ni = 0; ni < 8; ni++) {
            mx0 = fmaxf(mx0, fmaxf(s[ni][0], s[ni][1]));
            mx1 = fmaxf(mx1, fmaxf(s[ni][2], s[ni][3]));
        }
        mx0 = fmaxf(mx0, __shfl_xor_sync(0xffffffffu, mx0, 1));
        mx0 = fmaxf(mx0, __shfl_xor_sync(0xffffffffu, mx0, 2));
        mx1 = fmaxf(mx1, __shfl_xor_sync(0xffffffffu, mx1, 1));
        mx1 = fmaxf(mx1, __shfl_xor_sync(0xffffffffu, mx1, 2));

        float mn0 = fmaxf(mrow0, mx0), mn1 = fmaxf(mrow1, mx1);
        float c0 = ex2(mrow0 - mn0), c1 = ex2(mrow1 - mn1);
        float sum0 = 0.f, sum1 = 0.f;
        #pragma unroll
        for (int ni = 0; ni < 8; ni++) {
            s[ni][0] = ex2(s[ni][0] - mn0);
            s[ni][1] = ex2(s[ni][1] - mn0);
            s[ni][2] = ex2(s[ni][2] - mn1);
            s[ni][3] = ex2(s[ni][3] - mn1);
            sum0 += s[ni][0] + s[ni][1];
            sum1 += s[ni][2] + s[ni][3];
        }
        sum0 += __shfl_xor_sync(0xffffffffu, sum0, 1);
        sum0 += __shfl_xor_sync(0xffffffffu, sum0, 2);
        sum1 += __shfl_xor_sync(0xffffffffu, sum1, 1);
        sum1 += __shfl_xor_sync(0xffffffffu, sum1, 2);
        lrow0 = lrow0 * c0 + sum0;  mrow0 = mn0;
        lrow1 = lrow1 * c1 + sum1;  mrow1 = mn1;
        #pragma unroll
        for (int ni = 0; ni < 8; ni++) {
            o[ni][0] *= c0; o[ni][1] *= c0;
            o[ni][2] *= c1; o[ni][3] *= c1;
        }

        // ---- prefetch K[kt+1] (overlaps PV)
        __syncthreads();
        if (kt + 1 < NT) {
            const float* kn = ksrc + (size_t)(kt + 1) * 64 * EE;
            #pragma unroll
            for (int i = 0; i < 8; i++)
                cpa16(Ks_u + dstWK + i * 8 * KSTR * 4, kn + (size_t)i * 8 * EE);
            cp_commit();
            cp_wait1();
        } else {
            cp_wait0();
        }
        __syncthreads();

        // ---- write P (tf32) to warp-local rows of Ps
        {
            const int m = warp * 16;
            #pragma unroll
            for (int ni = 0; ni < 8; ni++) {
                uint2 w0 = make_uint2(f2tf(s[ni][0]), f2tf(s[ni][1]));
                uint2 w1 = make_uint2(f2tf(s[ni][2]), f2tf(s[ni][3]));
                *(uint2*)&Ps[(m + g)     * ASTR + ni * 8 + 2 * t] = w0;
                *(uint2*)&Ps[(m + g + 8) * ASTR + ni * 8 + 2 * t] = w1;
            }
        }
        __syncwarp();

        // ---- O += P @ V  (A from Ps, B from Vt via LDS.64)
        {
            const int m = warp * 16;
            #pragma unroll
            for (int ks = 0; ks < 8; ks++) {
                unsigned af[4];
                af[0] = Ps[(m + g)     * ASTR + ks * 8 + t];
                af[1] = Ps[(m + g + 8) * ASTR + ks * 8 + t];
                af[2] = Ps[(m + g)     * ASTR + ks * 8 + t + 4];
                af[3] = Ps[(m + g + 8) * ASTR + ks * 8 + t + 4];
                #pragma unroll
                for (int ni = 0; ni < 8; ni++) {
                    const int n = ni * 8 + g;
                    uint2 bv = *(const uint2*)(Vt + n * KSTR + ks * 8 + 2 * t);
                    unsigned bb[2] = { bv.x, bv.y };
                    mma_tf32(o[ni], af, bb);
                }
            }
        }
        __syncthreads();

        // ---- prefetch V[kt+1] (overlaps next S phase)
        if (kt + 1 < NT) {
            const float* vn = vsrc + (size_t)(kt + 1) * 64;
            #pragma unroll
            for (int i = 0; i < 8; i++)
                cpa16(Vt_u + dstWK + i * 8 * KSTR * 4, vn + (size_t)i * 8 * SS);
            cp_commit();
        }
    }

    // ---- normalize, round, store K-pair-permuted (consumed by out_gemm)
    float inv0 = 1.f / lrow0, inv1 = 1.f / lrow1;
    const int r0q = q0 + warp * 16 + g;
    #pragma unroll
    for (int ni = 0; ni < 8; ni++) {
        const int d = h * HD + ni * 8 + 2 * t;
        const int jj = d & 7;                       // = 2t
        const int p0 = ((jj & 3) << 1) + (jj >> 2);
        float* dst0 = g_att + (size_t)(b * SS + r0q)     * EE + (d & ~7);
        float* dst1 = g_att + (size_t)(b * SS + r0q + 8) * EE + (d & ~7);
        dst0[p0]     = __uint_as_float(f2tf(o[ni][0] * inv0));
        dst0[p0 + 2] = __uint_as_float(f2tf(o[ni][1] * inv0));
        dst1[p0]     = __uint_as_float(f2tf(o[ni][2] * inv1));
        dst1[p0 + 2] = __uint_as_float(f2tf(o[ni][3] * inv1));
    }
}

// ---------------------------------------------------------------------------
// Launch
// ---------------------------------------------------------------------------
extern "C" void kernel_launch(void* const* d_in, const int* in_sizes, int n_in,
                              void* d_out, int out_size)
{
    const float* query = (const float*)d_in[0];
    const float* key_  = (const float*)d_in[1];
    const float* value = (const float*)d_in[2];
    const float* Wq = (const float*)d_in[3];
    const float* bq = (const float*)d_in[4];
    const float* Wk = (const float*)d_in[5];
    const float* bk = (const float*)d_in[6];
    const float* Wv = (const float*)d_in[7];
    const float* bv = (const float*)d_in[8];
    const float* Wo = (const float*)d_in[9];
    const float* bo = (const float*)d_in[10];
    float* out = (float*)d_out;

    float *q, *k, *v, *att, *xq, *xk, *xv, *wq, *wk, *wv, *wo;
    cudaGetSymbolAddress((void**)&q,   g_q);
    cudaGetSymbolAddress((void**)&k,   g_k);
    cudaGetSymbolAddress((void**)&v,   g_v);
    cudaGetSymbolAddress((void**)&att, g_att);
    cudaGetSymbolAddress((void**)&xq,  g_xq);
    cudaGetSymbolAddress((void**)&xk,  g_xk);
    cudaGetSymbolAddress((void**)&xv,  g_xv);
    cudaGetSymbolAddress((void**)&wq,  g_wq);
    cudaGetSymbolAddress((void**)&wk,  g_wk);
    cudaGetSymbolAddress((void**)&wv,  g_wv);
    cudaGetSymbolAddress((void**)&wo,  g_wo);

    static bool attr_done = false;
    if (!attr_done) {
        cudaFuncSetAttribute(qkv_gemm, cudaFuncAttributeMaxDynamicSharedMemorySize, 2 * STG2B);
        cudaFuncSetAttribute(out_gemm, cudaFuncAttributeMaxDynamicSharedMemorySize, 2 * STG2B);
        cudaFuncSetAttribute(attn_tc,  cudaFuncAttributeMaxDynamicSharedMemorySize, ATT_SMEM_W * 4);
        attr_done = true;
    }

    // 1) prepass: round + K-pair-permute inputs and weights
    RoundArgs ra;
    ra.src[0] = query; ra.dst[0] = xq; ra.n4[0] = MTOT * EE / 4;
    ra.src[1] = key_;  ra.dst[1] = xk; ra.n4[1] = MTOT * EE / 4;
    ra.src[2] = value; ra.dst[2] = xv; ra.n4[2] = MTOT * EE / 4;
    ra.src[3] = Wq;    ra.dst[3] = wq; ra.n4[3] = EE * EE / 4;
    ra.src[4] = Wk;    ra.dst[4] = wk; ra.n4[4] = EE * EE / 4;
    ra.src[5] = Wv;    ra.dst[5] = wv; ra.n4[5] = EE * EE / 4;
    ra.src[6] = Wo;    ra.dst[6] = wo; ra.n4[6] = EE * EE / 4;
    tf32_round<<<dim3(1024, 7), 256>>>(ra);

    // 2) QKV projections (K pair-permuted out; V transposed+permuted out)
    QKVArgs args;
    args.A[0] = xq; args.A[1] = xk; args.A[2] = xv;
    args.W[0] = wq; args.W[1] = wk; args.W[2] = wv;
    args.bias[0] = bq; args.bias[1] = bk; args.bias[2] = bv;
    args.C[0] = q; args.C[1] = k; args.C[2] = v;
    qkv_gemm<<<dim3(EE / 128, MTOT / 128, 3), 256, 2 * STG2B>>>(args);

    // 3) attention
    attn_tc<<<dim3(BB * HH, SS / 64), 128, ATT_SMEM_W * 4>>>();

    // 4) output projection
    out_gemm<<<dim3(EE / 128, MTOT / 128), 256, 2 * STG2B>>>(att, wo, bo, out);
}

// round 13
// speedup vs baseline: 1.3004x; 1.0022x over previous
#include <cuda_runtime.h>
#include <math.h>

#define BB 2
#define SS 2048
#define EE 1024
#define HH 16
#define HD 64
#define MTOT (BB*SS)
#define SCALEL 0.1803368801111204f      // 0.125 * log2(e)

// Scratch (allocation-free rule): device globals
__device__ float g_q[MTOT * EE];     // Q projection (normal layout)
__device__ float g_k[MTOT * EE];     // K projection, chunk16-permuted head-dims (R13)
__device__ float g_v[MTOT * EE];     // V transposed [b*1024+h*64+d][s], s chunk16-permuted (R13)
__device__ float g_att[MTOT * EE];   // attention out, pair-permuted K cols (R12)
__device__ float g_xq[MTOT * EE];    // tf32-rounded + pair-permuted (R12)
__device__ float g_xk[MTOT * EE];
__device__ float g_xv[MTOT * EE];
__device__ float g_wq[EE * EE];
__device__ float g_wk[EE * EE];
__device__ float g_wv[EE * EE];
__device__ float g_wo[EE * EE];

// ---------------------------------------------------------------------------
// helpers
// ---------------------------------------------------------------------------
__device__ __forceinline__ unsigned f2tf(float f) {
    unsigned r;
    asm("cvt.rna.tf32.f32 %0, %1;" : "=r"(r) : "f"(f));
    return r;
}

__device__ __forceinline__ float ex2(float x) {
    float r;
    asm("ex2.approx.f32 %0, %1;" : "=f"(r) : "f"(x));
    return r;
}

// chunk16 position of k (0..63) within a 64-word block (R13 layout):
// chunk = (tc&1) | ((ks2>>1)<<1) | ((tc>>1)<<2) | ((ks2&1)<<3); word = chunk*4 + par*2 + half
__device__ __forceinline__ int kpos(int k) {
    const int j = k & 7, ks = k >> 3;
    const int tc = j & 3, half = j >> 2, ks2 = ks >> 1, par = ks & 1;
    const int chunk = (tc & 1) | ((ks2 >> 1) << 1) | ((tc >> 1) << 2) | ((ks2 & 1) << 3);
    return chunk * 4 + par * 2 + half;
}

__device__ __forceinline__ void mma_tf32(float c[4], const unsigned a[4], const unsigned b[2]) {
    asm volatile(
        "mma.sync.aligned.m16n8k8.row.col.f32.tf32.tf32.f32 "
        "{%0,%1,%2,%3}, {%4,%5,%6,%7}, {%8,%9}, {%0,%1,%2,%3};"
        : "+f"(c[0]), "+f"(c[1]), "+f"(c[2]), "+f"(c[3])
        : "r"(a[0]), "r"(a[1]), "r"(a[2]), "r"(a[3]), "r"(b[0]), "r"(b[1]));
}

__device__ __forceinline__ void cpa16(unsigned dst, const void* src) {
    asm volatile("cp.async.cg.shared.global [%0], [%1], 16;" :: "r"(dst), "l"(src) : "memory");
}
__device__ __forceinline__ void cp_commit() { asm volatile("cp.async.commit_group;" ::: "memory"); }
__device__ __forceinline__ void cp_wait0() { asm volatile("cp.async.wait_group 0;" ::: "memory"); }
__device__ __forceinline__ void cp_wait1() { asm volatile("cp.async.wait_group 1;" ::: "memory"); }
__device__ __forceinline__ void cp_wait2() { asm volatile("cp.async.wait_group 2;" ::: "memory"); }

// ---------------------------------------------------------------------------
// Prepass: round 7 tensors to tf32 AND pair-permute K-dim within 8-groups
// (GEMM operand layout, R12: pos(j)=(j%4)*2+j/4)
// ---------------------------------------------------------------------------
struct RoundArgs {
    const float* src[7];
    float*       dst[7];
    int          n4[7];
};

__global__ __launch_bounds__(256) void tf32_round(RoundArgs a) {
    const int z = blockIdx.y;
    const int n4 = a.n4[z];
    const float4* s = (const float4*)a.src[z];
    float* dst = a.dst[z];
    for (int i = blockIdx.x * blockDim.x + threadIdx.x; i < n4;
         i += gridDim.x * blockDim.x) {
        float4 v = s[i];
        float* db = dst + (((size_t)i & ~(size_t)1) << 2);  // group base
        const int off = i & 1;
        db[off + 0] = __uint_as_float(f2tf(v.x));
        db[off + 2] = __uint_as_float(f2tf(v.y));
        db[off + 4] = __uint_as_float(f2tf(v.z));
        db[off + 6] = __uint_as_float(f2tf(v.w));
    }
}

// ---------------------------------------------------------------------------
// GEMM: C[M,N] = A[M,K] @ W[N,K]^T + bias   (A, W tf32 + K-pair-permuted)
// R12: stride-40 smem, all fragments LDS.64, 2-stage cp.async pipeline.
// Out-PERM: 1 = chunk16-permute output head-dims (K proj, R13);
//           2 = transpose + chunk16-permute s (V, R13).
// ---------------------------------------------------------------------------
#define GSTR 40
#define STG2W (128 * GSTR * 2)   // 10240 words per stage
#define STG2B (STG2W * 4)

struct QKVArgs {
    const float* A[3];
    const float* W[3];
    const float* bias[3];
    float*       C[3];
};

template<bool RND, int PERM>
__device__ __forceinline__ void gemm_body(
    const float* __restrict__ A, const float* __restrict__ W,
    const float* __restrict__ bias, float* __restrict__ C)
{
    extern __shared__ unsigned sm[];   // 2 stages x 10240 words = 80 KB
    const unsigned smem_u = (unsigned)__cvta_generic_to_shared(sm);

    const int tid  = threadIdx.x;
    const int warp = tid >> 5, lane = tid & 31;
    const int g = lane >> 2, t = lane & 3;
    const int wm = warp & 1, wn = warp >> 1;     // 2 x 4 warps, warp tile 64x32
    const int bm = blockIdx.y * 128, bn = blockIdx.x * 128;

    const int kq = tid & 7;
    const int m0 = tid >> 3;
    const float* Asrc = A + (size_t)(bm + m0) * EE + kq * 4;
    const float* Wsrc = W + (size_t)(bn + m0) * EE + kq * 4;
    const unsigned dA = smem_u + (m0 * GSTR + kq * 4) * 4;
    const unsigned dB = dA + 128 * GSTR * 4;

    float acc[4][4][4] = {};
    const int NK = EE / 32;          // 32

    // prologue: stage tiles 0 and 1
    #pragma unroll
    for (int p = 0; p < 2; p++) {
        const unsigned so = p * STG2B;
        const int ko = p * 32;
        #pragma unroll
        for (int i = 0; i < 4; i++) {
            cpa16(dA + so + i * (32 * GSTR * 4), Asrc + ko + (size_t)i * 32 * EE);
            cpa16(dB + so + i * (32 * GSTR * 4), Wsrc + ko + (size_t)i * 32 * EE);
        }
        cp_commit();
    }

    for (int kt = 0; kt < NK; kt++) {
        if (kt + 1 < NK) cp_wait1(); else cp_wait0();
        __syncthreads();

        const unsigned* Asm = sm + (kt & 1) * STG2W;
        const unsigned* Bsm = Asm + 128 * GSTR;

        #pragma unroll
        for (int ksc = 0; ksc < 4; ksc++) {
            const int koff = ksc * 8 + 2 * t;
            unsigned af[4][4], bf[4][2];
            #pragma unroll
            for (int mi = 0; mi < 4; mi++) {
                const int row = wm * 64 + mi * 16;
                uint2 a0 = *(const uint2*)(Asm + (row + g)     * GSTR + koff);
                uint2 a1 = *(const uint2*)(Asm + (row + g + 8) * GSTR + koff);
                af[mi][0] = a0.x; af[mi][1] = a1.x; af[mi][2] = a0.y; af[mi][3] = a1.y;
            }
            #pragma unroll
            for (int ni = 0; ni < 4; ni++) {
                const int col = wn * 32 + ni * 8 + g;
                uint2 bv = *(const uint2*)(Bsm + col * GSTR + koff);
                bf[ni][0] = bv.x; bf[ni][1] = bv.y;
            }
            #pragma unroll
            for (int mi = 0; mi < 4; mi++)
                #pragma unroll
                for (int ni = 0; ni < 4; ni++)
                    mma_tf32(acc[mi][ni], af[mi], bf[ni]);
        }
        __syncthreads();

        if (kt + 2 < NK) {
            const unsigned so = (kt & 1) * STG2B;
            const int ko = (kt + 2) * 32;
            #pragma unroll
            for (int i = 0; i < 4; i++) {
                cpa16(dA + so + i * (32 * GSTR * 4), Asrc + ko + (size_t)i * 32 * EE);
                cpa16(dB + so + i * (32 * GSTR * 4), Wsrc + ko + (size_t)i * 32 * EE);
            }
            cp_commit();
        }
    }

    // ---- epilogue
    #pragma unroll
    for (int mi = 0; mi < 4; mi++) {
        #pragma unroll
        for (int r2 = 0; r2 < 2; r2++) {
            const int m = bm + wm * 64 + mi * 16 + g + r2 * 8;
            #pragma unroll
            for (int ni = 0; ni < 4; ni++) {
                const int n = bn + wn * 32 + ni * 8 + 2 * t;
                float2 bv = *(const float2*)(bias + n);
                float2 o;
                o.x = acc[mi][ni][r2 * 2 + 0] + bv.x;
                o.y = acc[mi][ni][r2 * 2 + 1] + bv.y;
                if (RND) {
                    o.x = __uint_as_float(f2tf(o.x));
                    o.y = __uint_as_float(f2tf(o.y));
                }
                if (PERM == 1) {
                    // K: chunk16-permute head-dims within 64-block (R13)
                    const int D = n & 63;
                    float* dst = C + (size_t)m * EE + (n & ~63);
                    dst[kpos(D)]     = o.x;
                    dst[kpos(D + 1)] = o.y;
                } else if (PERM == 2) {
                    // V: transpose to [b*1024+n][s], s chunk16-permuted (R13)
                    const int bI = m >> 11;
                    const int sI = m & 2047;
                    const int scol = (sI & ~63) | kpos(sI & 63);
                    float* dst = C + (size_t)(bI * 1024 + n) * SS + scol;
                    dst[0]  = o.x;
                    dst[SS] = o.y;
                } else {
                    *(float2*)(C + (size_t)m * EE + n) = o;
                }
            }
        }
    }
}

__global__ __launch_bounds__(256, 2) void qkv_gemm(QKVArgs args) {
    const int z = blockIdx.z;
    if (z == 0)
        gemm_body<true, 0>(args.A[0], args.W[0], args.bias[0], args.C[0]);
    else if (z == 1)
        gemm_body<true, 1>(args.A[1], args.W[1], args.bias[1], args.C[1]);
    else
        gemm_body<true, 2>(args.A[2], args.W[2], args.bias[2], args.C[2]);
}

__global__ __launch_bounds__(256, 2) void out_gemm(const float* __restrict__ A,
                                                   const float* __restrict__ W,
                                                   const float* __restrict__ bias,
                                                   float* __restrict__ C) {
    gemm_body<false, 0>(A, W, bias, C);
}

// ---------------------------------------------------------------------------
// Flash attention, tf32 mma, cp.async pipelined staging.
// Block = (b, h, 64 q-rows), 128 threads (4 warps, 16 rows each), 4 CTAs/SM.
// R13: K and V in chunk16 layout -> B-fragments for a ks-PAIR via one LDS.128
// (banks (2g+chunk) mod 8 distinct per phase at stride 72).
// Log2-domain softmax (R11); g_att stored pair-permuted for out_gemm (R12).
// ---------------------------------------------------------------------------
#define ASTR 68
#define KSTR 72
#define ATT_SMEM_W 13568   // Ks 4608 | Vt 4608 | Ps 4352 words (53 KB)

__global__ __launch_bounds__(128, 4) void attn_tc() {
    extern __shared__ unsigned smem[];
    unsigned* Ks = smem;                 // 4608 words (stride 72)
    unsigned* Vt = smem + 4608;          // 4608 words (stride 72)
    unsigned* Ps = smem + 9216;          // 4352 words (Q staging, then P tiles)
    const unsigned smem_u = (unsigned)__cvta_generic_to_shared(smem);
    const unsigned Ks_u = smem_u;
    const unsigned Vt_u = smem_u + 4608 * 4;
    const unsigned Ps_u = smem_u + 9216 * 4;

    const int tid  = threadIdx.x;
    const int warp = tid >> 5, lane = tid & 31;
    const int g = lane >> 2, t = lane & 3;
    const int bh = blockIdx.x;
    const int b = bh >> 4, h = bh & 15;
    const int q0 = blockIdx.y * 64;

    const size_t base = (size_t)b * SS * EE + (size_t)h * HD;

    const int r0 = tid >> 4;
    const int c4 = tid & 15;
    const unsigned dstW  = (unsigned)((r0 * ASTR + c4 * 4) * 4);
    const unsigned dstWK = (unsigned)((r0 * KSTR + c4 * 4) * 4);

    const float* qsrc = g_q + base + (size_t)(q0 + r0) * EE + c4 * 4;
    const float* ksrc = g_k + base + (size_t)r0 * EE + c4 * 4;
    const float* vsrc = g_v + (size_t)(b * 1024 + h * HD + r0) * SS + c4 * 4;

    // ---- prologue: Q -> Ps, K0 -> Ks, V0 -> Vt
    #pragma unroll
    for (int i = 0; i < 8; i++)
        cpa16(Ps_u + dstW + i * 8 * ASTR * 4, qsrc + (size_t)i * 8 * EE);
    cp_commit();
    #pragma unroll
    for (int i = 0; i < 8; i++)
        cpa16(Ks_u + dstWK + i * 8 * KSTR * 4, ksrc + (size_t)i * 8 * EE);
    cp_commit();
    #pragma unroll
    for (int i = 0; i < 8; i++)
        cpa16(Vt_u + dstWK + i * 8 * KSTR * 4, vsrc + (size_t)i * 8 * SS);
    cp_commit();

    cp_wait2();
    __syncthreads();

    // pull Q A-fragments, fold 0.125*log2(e)
    unsigned qf[8][4];
    {
        const int m = warp * 16;
        #pragma unroll
        for (int ks = 0; ks < 8; ks++) {
            qf[ks][0] = Ps[(m + g)     * ASTR + ks * 8 + t];
            qf[ks][1] = Ps[(m + g + 8) * ASTR + ks * 8 + t];
            qf[ks][2] = Ps[(m + g)     * ASTR + ks * 8 + t + 4];
            qf[ks][3] = Ps[(m + g + 8) * ASTR + ks * 8 + t + 4];
            #pragma unroll
            for (int j = 0; j < 4; j++)
                qf[ks][j] = f2tf(__uint_as_float(qf[ks][j]) * SCALEL);
        }
    }

    // per-lane chunk offsets for the 4 ks-pairs (R13)
    int ck[4];
    #pragma unroll
    for (int ks2 = 0; ks2 < 4; ks2++)
        ck[ks2] = ((t & 1) | ((ks2 >> 1) << 1) | ((t >> 1) << 2) | ((ks2 & 1) << 3)) << 2;

    float o[8][4] = {};
    float mrow0 = -1e30f, mrow1 = -1e30f, lrow0 = 0.f, lrow1 = 0.f;

    const int NT = SS / 64;
    for (int kt = 0; kt < NT; kt++) {
        cp_wait1();
        __syncthreads();

        // ---- S = Q @ K^T (log2-domain); ks-pair B-frags via LDS.128
        float s[8][4] = {};
        #pragma unroll
        for (int ks2 = 0; ks2 < 4; ks2++) {
            #pragma unroll
            for (int ni = 0; ni < 8; ni++) {
                const int n = ni * 8 + g;
                uint4 v = *(const uint4*)(Ks + n * KSTR + ck[ks2]);
                unsigned b0[2] = { v.x, v.y };
                unsigned b1[2] = { v.z, v.w };
                mma_tf32(s[ni], qf[2 * ks2],     b0);
                mma_tf32(s[ni], qf[2 * ks2 + 1], b1);
            }
        }

        // ---- online softmax (log2 domain)
        float mx0 = -1e30f, mx1 = -1e30f;
        #pragma unroll
        for (int ni = 0; ni < 8; ni++) {
            mx0 = fmaxf(mx0, fmaxf(s[ni][0], s[ni][1]));
            mx1 = fmaxf(mx1, fmaxf(s[ni][2], s[ni][3]));
        }
        mx0 = fmaxf(mx0, __shfl_xor_sync(0xffffffffu, mx0, 1));
        mx0 = fmaxf(mx0, __shfl_xor_sync(0xffffffffu, mx0, 2));
        mx1 = fmaxf(mx1, __shfl_xor_sync(0xffffffffu, mx1, 1));
        mx1 = fmaxf(mx1, __shfl_xor_sync(0xffffffffu, mx1, 2));

        float mn0 = fmaxf(mrow0, mx0), mn1 = fmaxf(mrow1, mx1);
        float c0 = ex2(mrow0 - mn0), c1 = ex2(mrow1 - mn1);
        float sum0 = 0.f, sum1 = 0.f;
        #pragma unroll
        for (int ni = 0; ni < 8; ni++) {
            s[ni][0] = ex2(s[ni][0] - mn0);
            s[ni][1] = ex2(s[ni][1] - mn0);
            s[ni][2] = ex2(s[ni][2] - mn1);
            s[ni][3] = ex2(s[ni][3] - mn1);
            sum0 += s[ni][0] + s[ni][1];
            sum1 += s[ni][2] + s[ni][3];
        }
        sum0 += __shfl_xor_sync(0xffffffffu, sum0, 1);
        sum0 += __shfl_xor_sync(0xffffffffu, sum0, 2);
        sum1 += __shfl_xor_sync(0xffffffffu, sum1, 1);
        sum1 += __shfl_xor_sync(0xffffffffu, sum1, 2);
        lrow0 = lrow0 * c0 + sum0;  mrow0 = mn0;
        lrow1 = lrow1 * c1 + sum1;  mrow1 = mn1;
        #pragma unroll
        for (int ni = 0; ni < 8; ni++) {
            o[ni][0] *= c0; o[ni][1] *= c0;
            o[ni][2] *= c1; o[ni][3] *= c1;
        }

        // ---- prefetch K[kt+1] (overlaps PV)
        __syncthreads();
        if (kt + 1 < NT) {
            const float* kn = ksrc + (size_t)(kt + 1) * 64 * EE;
            #pragma unroll
            for (int i = 0; i < 8; i++)
                cpa16(Ks_u + dstWK + i * 8 * KSTR * 4, kn + (size_t)i * 8 * EE);
            cp_commit();
            cp_wait1();
        } else {
            cp_wait0();
        }
        __syncthreads();

        // ---- write P (tf32) to warp-local rows of Ps
        {
            const int m = warp * 16;
            #pragma unroll
            for (int ni = 0; ni < 8; ni++) {
                uint2 w0 = make_uint2(f2tf(s[ni][0]), f2tf(s[ni][1]));
                uint2 w1 = make_uint2(f2tf(s[ni][2]), f2tf(s[ni][3]));
                *(uint2*)&Ps[(m + g)     * ASTR + ni * 8 + 2 * t] = w0;
                *(uint2*)&Ps[(m + g + 8) * ASTR + ni * 8 + 2 * t] = w1;
            }
        }
        __syncwarp();

        // ---- O += P @ V  (A from Ps; ks-pair B-frags from Vt via LDS.128)
        {
            const int m = warp * 16;
            #pragma unroll
            for (int ks2 = 0; ks2 < 4; ks2++) {
                unsigned afA[4], afB[4];
                const int kA = 2 * ks2, kB = 2 * ks2 + 1;
                afA[0] = Ps[(m + g)     * ASTR + kA * 8 + t];
                afA[1] = Ps[(m + g + 8) * ASTR + kA * 8 + t];
                afA[2] = Ps[(m + g)     * ASTR + kA * 8 + t + 4];
                afA[3] = Ps[(m + g + 8) * ASTR + kA * 8 + t + 4];
                afB[0] = Ps[(m + g)     * ASTR + kB * 8 + t];
                afB[1] = Ps[(m + g + 8) * ASTR + kB * 8 + t];
                afB[2] = Ps[(m + g)     * ASTR + kB * 8 + t + 4];
                afB[3] = Ps[(m + g + 8) * ASTR + kB * 8 + t + 4];
                #pragma unroll
                for (int ni = 0; ni < 8; ni++) {
                    const int n = ni * 8 + g;
                    uint4 v = *(const uint4*)(Vt + n * KSTR + ck[ks2]);
                    unsigned b0[2] = { v.x, v.y };
                    unsigned b1[2] = { v.z, v.w };
                    mma_tf32(o[ni], afA, b0);
                    mma_tf32(o[ni], afB, b1);
                }
            }
        }
        __syncthreads();

        // ---- prefetch V[kt+1] (overlaps next S phase)
        if (kt + 1 < NT) {
            const float* vn = vsrc + (size_t)(kt + 1) * 64;
            #pragma unroll
            for (int i = 0; i < 8; i++)
                cpa16(Vt_u + dstWK + i * 8 * KSTR * 4, vn + (size_t)i * 8 * SS);
            cp_commit();
        }
    }

    // ---- normalize, round, store pair-permuted (R12 layout for out_gemm)
    float inv0 = 1.f / lrow0, inv1 = 1.f / lrow1;
    const int r0q = q0 + warp * 16 + g;
    #pragma unroll
    for (int ni = 0; ni < 8; ni++) {
        const int d = h * HD + ni * 8 + 2 * t;
        const int jj = d & 7;
        const int p0 = ((jj & 3) << 1) + (jj >> 2);
        float* dst0 = g_att + (size_t)(b * SS + r0q)     * EE + (d & ~7);
        float* dst1 = g_att + (size_t)(b * SS + r0q + 8) * EE + (d & ~7);
        dst0[p0]     = __uint_as_float(f2tf(o[ni][0] * inv0));
        dst0[p0 + 2] = __uint_as_float(f2tf(o[ni][1] * inv0));
        dst1[p0]     = __uint_as_float(f2tf(o[ni][2] * inv1));
        dst1[p0 + 2] = __uint_as_float(f2tf(o[ni][3] * inv1));
    }
}

// ---------------------------------------------------------------------------
// Launch
// ---------------------------------------------------------------------------
extern "C" void kernel_launch(void* const* d_in, const int* in_sizes, int n_in,
                              void* d_out, int out_size)
{
    const float* query = (const float*)d_in[0];
    const float* key_  = (const float*)d_in[1];
    const float* value = (const float*)d_in[2];
    const float* Wq = (const float*)d_in[3];
    const float* bq = (const float*)d_in[4];
    const float* Wk = (const float*)d_in[5];
    const float* bk = (const float*)d_in[6];
    const float* Wv = (const float*)d_in[7];
    const float* bv = (const float*)d_in[8];
    const float* Wo = (const float*)d_in[9];
    const float* bo = (const float*)d_in[10];
    float* out = (float*)d_out;

    float *q, *k, *v, *att, *xq, *xk, *xv, *wq, *wk, *wv, *wo;
    cudaGetSymbolAddress((void**)&q,   g_q);
    cudaGetSymbolAddress((void**)&k,   g_k);
    cudaGetSymbolAddress((void**)&v,   g_v);
    cudaGetSymbolAddress((void**)&att, g_att);
    cudaGetSymbolAddress((void**)&xq,  g_xq);
    cudaGetSymbolAddress((void**)&xk,  g_xk);
    cudaGetSymbolAddress((void**)&xv,  g_xv);
    cudaGetSymbolAddress((void**)&wq,  g_wq);
    cudaGetSymbolAddress((void**)&wk,  g_wk);
    cudaGetSymbolAddress((void**)&wv,  g_wv);
    cudaGetSymbolAddress((void**)&wo,  g_wo);

    static bool attr_done = false;
    if (!attr_done) {
        cudaFuncSetAttribute(qkv_gemm, cudaFuncAttributeMaxDynamicSharedMemorySize, 2 * STG2B);
        cudaFuncSetAttribute(out_gemm, cudaFuncAttributeMaxDynamicSharedMemorySize, 2 * STG2B);
        cudaFuncSetAttribute(attn_tc,  cudaFuncAttributeMaxDynamicSharedMemorySize, ATT_SMEM_W * 4);
        attr_done = true;
    }

    // 1) prepass: round + pair-permute inputs and weights (GEMM layout)
    RoundArgs ra;
    ra.src[0] = query; ra.dst[0] = xq; ra.n4[0] = MTOT * EE / 4;
    ra.src[1] = key_;  ra.dst[1] = xk; ra.n4[1] = MTOT * EE / 4;
    ra.src[2] = value; ra.dst[2] = xv; ra.n4[2] = MTOT * EE / 4;
    ra.src[3] = Wq;    ra.dst[3] = wq; ra.n4[3] = EE * EE / 4;
    ra.src[4] = Wk;    ra.dst[4] = wk; ra.n4[4] = EE * EE / 4;
    ra.src[5] = Wv;    ra.dst[5] = wv; ra.n4[5] = EE * EE / 4;
    ra.src[6] = Wo;    ra.dst[6] = wo; ra.n4[6] = EE * EE / 4;
    tf32_round<<<dim3(1024, 7), 256>>>(ra);

    // 2) QKV projections (K chunk16-permuted out; V transposed+chunk16 out)
    QKVArgs args;
    args.A[0] = xq; args.A[1] = xk; args.A[2] = xv;
    args.W[0] = wq; args.W[1] = wk; args.W[2] = wv;
    args.bias[0] = bq; args.bias[1] = bk; args.bias[2] = bv;
    args.C[0] = q; args.C[1] = k; args.C[2] = v;
    qkv_gemm<<<dim3(EE / 128, MTOT / 128, 3), 256, 2 * STG2B>>>(args);

    // 3) attention
    attn_tc<<<dim3(BB * HH, SS / 64), 128, ATT_SMEM_W * 4>>>();

    // 4) output projection
    out_gemm<<<dim3(EE / 128, MTOT / 128), 256, 2 * STG2B>>>(att, wo, bo, out);
}